// round 12
// baseline (speedup 1.0000x reference)
#include <cuda_runtime.h>
#include <cuda_bf16.h>
#include <cuda_fp16.h>
#include <math.h>
#include <stddef.h>
#include <stdint.h>

// ---------------- problem constants ----------------
#define NUSR 50000
#define NITM 20000
#define NEDG 400000
#define FIN0 128
#define FHID 256
#define NHEAD 4

// ---------------- device scratch (no allocs allowed) ----------------
__device__ float g_hu [(size_t)NUSR * FHID];
__device__ float g_hi [(size_t)NITM * FHID];
__device__ __half g_hsu[(size_t)NUSR * FHID];   // projected feats, fp16 (gather-only)
__device__ __half g_hsi[(size_t)NITM * FHID];
__device__ float g_nu [(size_t)NUSR * FHID];
__device__ float g_ni [(size_t)NITM * FHID];
__device__ float g_el_u[NUSR * 4];
__device__ float g_el_i[NITM * 4];
__device__ int   g_rp_i[NITM + 1];
__device__ int   g_rp_u[NUSR + 1];
__device__ int   g_srcs_i[NEDG];
__device__ int   g_srcs_u[NEDG];
__device__ int   g_cur_i[NITM];
__device__ int   g_cur_u[NUSR];
__device__ float g_Vui[4 * FHID * NHEAD];
__device__ float g_Viu[4 * FHID * NHEAD];
__device__ float g_stats_i[3 * 512];
__device__ float g_stats_u[3 * 512];
__device__ int   g_part[64];
__device__ __nv_bfloat16 g_WHu[196608];
__device__ __nv_bfloat16 g_WLu[196608];
__device__ __nv_bfloat16 g_WHi[196608];
__device__ __nv_bfloat16 g_WLi[196608];
__device__ __nv_bfloat16 g_Auh[(size_t)NUSR * FHID];
__device__ __nv_bfloat16 g_Aul[(size_t)NUSR * FHID];
__device__ __nv_bfloat16 g_Aih[(size_t)NITM * FHID];
__device__ __nv_bfloat16 g_Ail[(size_t)NITM * FHID];

// ---------------- PTX helpers (baseline features only) ----------------
__device__ __forceinline__ uint32_t smem_u32(const void* p) {
    uint32_t a;
    asm("{ .reg .u64 t; cvta.to.shared.u64 t, %1; cvt.u32.u64 %0, t; }"
        : "=r"(a) : "l"(p));
    return a;
}
__device__ __forceinline__ void ldsm4(uint32_t* r, uint32_t addr) {
    asm volatile("ldmatrix.sync.aligned.m8n8.x4.shared.b16 {%0,%1,%2,%3}, [%4];"
        : "=r"(r[0]), "=r"(r[1]), "=r"(r[2]), "=r"(r[3]) : "r"(addr));
}
__device__ __forceinline__ void ldsm4t(uint32_t* r, uint32_t addr) {
    asm volatile("ldmatrix.sync.aligned.m8n8.x4.trans.shared.b16 {%0,%1,%2,%3}, [%4];"
        : "=r"(r[0]), "=r"(r[1]), "=r"(r[2]), "=r"(r[3]) : "r"(addr));
}
__device__ __forceinline__ void mma16816(float* c, const uint32_t* a,
                                         uint32_t b0, uint32_t b1) {
    asm volatile(
        "mma.sync.aligned.m16n8k16.row.col.f32.bf16.bf16.f32 "
        "{%0,%1,%2,%3}, {%4,%5,%6,%7}, {%8,%9}, {%0,%1,%2,%3};"
        : "+f"(c[0]), "+f"(c[1]), "+f"(c[2]), "+f"(c[3])
        : "r"(a[0]), "r"(a[1]), "r"(a[2]), "r"(a[3]), "r"(b0), "r"(b1));
}
#define CPA16(dst, src) \
    asm volatile("cp.async.cg.shared.global [%0], [%1], 16;" \
                 :: "r"(dst), "l"(src))
#define CP_COMMIT() asm volatile("cp.async.commit_group;")
#define CP_WAIT1()  asm volatile("cp.async.wait_group 1;" ::: "memory")
#define CP_WAIT0()  asm volatile("cp.async.wait_group 0;" ::: "memory")

__device__ __forceinline__ uint32_t pack_bf16x2(float a, float b) {
    return ((uint32_t)__bfloat16_as_ushort(__float2bfloat16_rn(b)) << 16) |
           __bfloat16_as_ushort(__float2bfloat16_rn(a));
}
__device__ __forceinline__ float fast_tanh(float x) {
    x = fminf(fmaxf(x, -15.f), 15.f);
    float e = __expf(2.f * x);
    return (e - 1.f) / (e + 1.f);
}

// ---------------- tiny utility kernels ----------------
__global__ void k_noop() {}
__global__ void k_zeroi(int* p, int n) {
    int i = blockIdx.x * blockDim.x + threadIdx.x;
    if (i < n) p[i] = 0;
}
__global__ void k_zerof(float* p, int n) {
    int i = blockIdx.x * blockDim.x + threadIdx.x;
    if (i < n) p[i] = 0.f;
}
__global__ void k_copyi(const int* __restrict__ a, int* __restrict__ b, int n) {
    int i = blockIdx.x * blockDim.x + threadIdx.x;
    if (i < n) b[i] = a[i];
}

// ---------------- CSR construction ----------------
__global__ void k_count(const int* __restrict__ eu, const int* __restrict__ ei,
                        int* cu, int* ci) {
    int k = blockIdx.x * blockDim.x + threadIdx.x;
    if (k < NEDG) {
        atomicAdd(&ci[ei[k]], 1);
        atomicAdd(&cu[eu[k]], 1);
    }
}
__global__ void k_scan_blk(const int* __restrict__ cnt, int n,
                           int* __restrict__ rp, int* __restrict__ part) {
    __shared__ int ws[32];
    int tid = threadIdx.x;
    int i = blockIdx.x * 1024 + tid;
    int v = (i < n) ? cnt[i] : 0;
    int lane = tid & 31, w = tid >> 5;
    int x = v;
    #pragma unroll
    for (int o = 1; o < 32; o <<= 1) {
        int y = __shfl_up_sync(0xffffffffu, x, o);
        if (lane >= o) x += y;
    }
    if (lane == 31) ws[w] = x;
    __syncthreads();
    if (w == 0) {
        int t = ws[lane];
        #pragma unroll
        for (int o = 1; o < 32; o <<= 1) {
            int y = __shfl_up_sync(0xffffffffu, t, o);
            if (lane >= o) t += y;
        }
        ws[lane] = t;
    }
    __syncthreads();
    int incl = x + (w > 0 ? ws[w - 1] : 0);
    if (i < n) rp[i + 1] = incl;
    if (tid == 1023) part[blockIdx.x] = incl;
}
__global__ void k_scan_part(int* part, int nb) {
    __shared__ int w0sum;
    int tid = threadIdx.x;
    int v = (tid < nb) ? part[tid] : 0;
    int lane = tid & 31, w = tid >> 5;
    int x = v;
    #pragma unroll
    for (int o = 1; o < 32; o <<= 1) {
        int y = __shfl_up_sync(0xffffffffu, x, o);
        if (lane >= o) x += y;
    }
    if (w == 0 && lane == 31) w0sum = x;
    __syncthreads();
    int incl = x + (w ? w0sum : 0);
    if (tid < nb) part[tid] = incl - v;
}
__global__ void k_scan_add(int* __restrict__ rp, const int* __restrict__ part, int n) {
    int i = blockIdx.x * 1024 + threadIdx.x;
    if (i < n) rp[i + 1] += part[blockIdx.x];
    if (i == 0) rp[0] = 0;
}
__global__ void k_scatter(const int* __restrict__ eu, const int* __restrict__ ei,
                          int* cu, int* ci,
                          int* __restrict__ su, int* __restrict__ si) {
    int k = blockIdx.x * blockDim.x + threadIdx.x;
    if (k < NEDG) {
        int u = eu[k], it = ei[k];
        int p = atomicAdd(&ci[it], 1);
        si[p] = u;
        int q = atomicAdd(&cu[u], 1);
        su[q] = it;
    }
}

// ------- vectorized fp32 -> bf16 hi/lo split: 4 elems per thread -------
__global__ void k_split4(const float4* __restrict__ X, uint2* __restrict__ xh,
                         uint2* __restrict__ xl, int total4) {
    int id = blockIdx.x * blockDim.x + threadIdx.x;
    if (id >= total4) return;
    float4 v = X[id];
    float hx = __bfloat162float(__float2bfloat16_rn(v.x));
    float hy = __bfloat162float(__float2bfloat16_rn(v.y));
    float hz = __bfloat162float(__float2bfloat16_rn(v.z));
    float hw = __bfloat162float(__float2bfloat16_rn(v.w));
    xh[id] = make_uint2(pack_bf16x2(v.x, v.y), pack_bf16x2(v.z, v.w));
    xl[id] = make_uint2(pack_bf16x2(v.x - hx, v.y - hy),
                        pack_bf16x2(v.z - hz, v.w - hw));
}

// ---------------- batched collapseV ----------------
struct CVArgs { const float* W[8]; const float* A[8]; };
__global__ void k_collapseAll(CVArgs a, float* __restrict__ Vui,
                              float* __restrict__ Viu) {
    int t = blockIdx.x * blockDim.x + threadIdx.x;
    if (t >= 7168) return;
    int side = (t >= 3584) ? 1 : 0;
    int u = t - side * 3584;
    int L, off;
    if (u < 512)       { L = 0; off = 0; }
    else if (u < 1536) { L = 1; off = 512; }
    else if (u < 2560) { L = 2; off = 1536; }
    else               { L = 3; off = 2560; }
    int local = u - off;
    int k = local >> 2, h = local & 3;
    int F = (L == 3) ? 128 : 256;
    int dh = (L == 3) ? 32 : 64;
    const float* W = a.W[side * 4 + L];
    const float* A1 = a.A[side * 4 + L] + NHEAD * dh;
    float s = 0.f;
    for (int d = 0; d < dh; d++)
        s += W[(size_t)k * F + h * dh + d] * A1[h * dh + d];
    (side ? Viu : Vui)[L * FHID * NHEAD + local] = s;
}

// ------ tensor-core GEMM + fused el epilogue; C stored fp16 (gather-only) ------
template <int BN, int DH>
__global__ void __launch_bounds__((BN == 256) ? 512 : 256, 1)
k_mma_gemm(const __nv_bfloat16* __restrict__ Ah, const __nv_bfloat16* __restrict__ Al,
           const __nv_bfloat16* __restrict__ Bh, const __nv_bfloat16* __restrict__ Bl,
           const float* __restrict__ attA,
           __half* __restrict__ C, float* __restrict__ el, int M, int K) {
    constexpr int NT = (BN == 256) ? 512 : 256;
    constexpr int SBSTR = BN * 2 + 16;
    constexpr int ASZ = 128 * 80;
    constexpr int BOFF = 2 * ASZ;
    constexpr int BSZ = 32 * SBSTR;
    constexpr int STAGE = BOFF + 2 * BSZ;
    constexpr int NBC = 32 * (BN / 8);

    extern __shared__ char smem[];
    uint32_t sb = smem_u32(smem);
    int tid = threadIdx.x;
    int wid = tid >> 5, lane = tid & 31;
    int wm = wid & 3, wn = wid >> 2;
    int bm = blockIdx.x * 128;

    float acc[2][8][4];
    #pragma unroll
    for (int i = 0; i < 2; i++)
        #pragma unroll
        for (int j = 0; j < 8; j++)
            #pragma unroll
            for (int q = 0; q < 4; q++) acc[i][j][q] = 0.f;

    int nch = K >> 5;

    auto load_stage = [&](int st, int kc) {
        uint32_t sbase = sb + st * STAGE;
        int k0 = kc << 5;
        #pragma unroll
        for (int c = tid; c < 512; c += NT) {
            int row = c >> 2, q = c & 3;
            int gr = bm + row;
            gr = gr < M ? gr : M - 1;
            size_t gi = (size_t)gr * K + k0 + q * 8;
            uint32_t d = sbase + row * 80 + q * 16;
            CPA16(d, Ah + gi);
            CPA16(d + ASZ, Al + gi);
        }
        #pragma unroll
        for (int c = tid; c < NBC; c += NT) {
            int k = c / (BN / 8), seg = c % (BN / 8);
            size_t gi = (size_t)(k0 + k) * BN + seg * 8;
            uint32_t d = sbase + BOFF + k * SBSTR + seg * 16;
            CPA16(d, Bh + gi);
            CPA16(d + BSZ, Bl + gi);
        }
        CP_COMMIT();
    };

    load_stage(0, 0);
    for (int kc = 0; kc < nch; kc++) {
        int cur = kc & 1;
        if (kc + 1 < nch) {
            load_stage(1 - cur, kc + 1);
            CP_WAIT1();
        } else {
            CP_WAIT0();
        }
        __syncthreads();
        uint32_t abase = sb + cur * STAGE;
        #pragma unroll
        for (int s = 0; s < 2; s++) {
            uint32_t Af[2][4], Alf[2][4];
            #pragma unroll
            for (int mt = 0; mt < 2; mt++) {
                uint32_t ad = abase +
                    (uint32_t)(wm * 32 + mt * 16 + (lane & 15)) * 80 +
                    s * 32 + (lane >> 4) * 16;
                ldsm4(Af[mt], ad);
                ldsm4(Alf[mt], ad + ASZ);
            }
            #pragma unroll
            for (int np = 0; np < 4; np++) {
                int g = lane >> 3, r = lane & 7;
                int kk = s * 16 + (g & 1) * 8 + r;
                int nn = wn * 64 + np * 16 + (g >> 1) * 8;
                uint32_t bd = abase + BOFF + (uint32_t)kk * SBSTR + nn * 2;
                uint32_t bh4[4], bl4[4];
                ldsm4t(bh4, bd);
                ldsm4t(bl4, bd + BSZ);
                #pragma unroll
                for (int mt = 0; mt < 2; mt++)
                    #pragma unroll
                    for (int sub = 0; sub < 2; sub++) {
                        float* a = acc[mt][np * 2 + sub];
                        mma16816(a, Af[mt], bh4[2 * sub], bh4[2 * sub + 1]);
                        mma16816(a, Af[mt], bl4[2 * sub], bl4[2 * sub + 1]);
                        mma16816(a, Alf[mt], bh4[2 * sub], bh4[2 * sub + 1]);
                    }
            }
        }
        __syncthreads();
    }

    constexpr int HPW = 64 / DH;
    int grp = lane >> 2, tq = lane & 3;
    #pragma unroll
    for (int mt = 0; mt < 2; mt++) {
        int r0 = bm + wm * 32 + mt * 16 + grp;
        int r1 = r0 + 8;
        #pragma unroll
        for (int nt = 0; nt < 8; nt++) {
            int col = wn * 64 + nt * 8 + tq * 2;
            if (r0 < M)
                *(__half2*)(C + (size_t)r0 * BN + col) =
                    __floats2half2_rn(acc[mt][nt][0], acc[mt][nt][1]);
            if (r1 < M)
                *(__half2*)(C + (size_t)r1 * BN + col) =
                    __floats2half2_rn(acc[mt][nt][2], acc[mt][nt][3]);
        }
        float s0[HPW], s1[HPW];
        #pragma unroll
        for (int p = 0; p < HPW; p++) { s0[p] = 0.f; s1[p] = 0.f; }
        #pragma unroll
        for (int nt = 0; nt < 8; nt++) {
            int part = (nt * 8) / DH;
            int col = wn * 64 + nt * 8 + tq * 2;
            float c0 = attA[col], c1 = attA[col + 1];
            s0[part] += c0 * acc[mt][nt][0] + c1 * acc[mt][nt][1];
            s1[part] += c0 * acc[mt][nt][2] + c1 * acc[mt][nt][3];
        }
        #pragma unroll
        for (int p = 0; p < HPW; p++) {
            s0[p] += __shfl_xor_sync(0xffffffffu, s0[p], 1);
            s0[p] += __shfl_xor_sync(0xffffffffu, s0[p], 2);
            s1[p] += __shfl_xor_sync(0xffffffffu, s1[p], 1);
            s1[p] += __shfl_xor_sync(0xffffffffu, s1[p], 2);
            if (tq == 0) {
                int h = wn * HPW + p;
                if (r0 < M) el[r0 * 4 + h] = s0[p];
                if (r1 < M) el[r1 * 4 + h] = s1[p];
            }
        }
    }
}

__device__ __forceinline__ float lrelu(float x, float s) { return x > 0.f ? x : s * x; }

// ---- fused edge kernel, F=256: er + 1-pass softmax-agg + BN stats; hs fp16 ----
__global__ void __launch_bounds__(256)
k_edge256s(const int* __restrict__ rp, const int* __restrict__ srcs,
           const float4* __restrict__ el4, const float4* __restrict__ V4,
           const float* __restrict__ cdst, const __half* __restrict__ hs,
           float* __restrict__ out, float* __restrict__ stats,
           int ndst, int fin) {
    __shared__ float s_st[512];
    int tid = threadIdx.x;
    for (int i = tid; i < 512; i += 256) s_st[i] = 0.f;
    __syncthreads();
    int lane = tid & 31, wloc = tid >> 5;
    bool loHalf = lane < 16;
    float sm0[4] = {0.f, 0.f, 0.f, 0.f}, sq0[4] = {0.f, 0.f, 0.f, 0.f};
    float sm1[4] = {0.f, 0.f, 0.f, 0.f}, sq1[4] = {0.f, 0.f, 0.f, 0.f};

    for (int w = blockIdx.x * 8 + wloc; w < ndst; w += gridDim.x * 8) {
        const float* c = cdst + (size_t)w * fin;
        float a0 = 0.f, a1 = 0.f, a2 = 0.f, a3 = 0.f;
        for (int k = lane; k < fin; k += 32) {
            float xv = c[k];
            float4 v = V4[k];
            a0 += xv * v.x; a1 += xv * v.y; a2 += xv * v.z; a3 += xv * v.w;
        }
        #pragma unroll
        for (int o = 16; o; o >>= 1) {
            a0 += __shfl_xor_sync(0xffffffffu, a0, o);
            a1 += __shfl_xor_sync(0xffffffffu, a1, o);
            a2 += __shfl_xor_sync(0xffffffffu, a2, o);
            a3 += __shfl_xor_sync(0xffffffffu, a3, o);
        }
        float erA = loHalf ? a0 : a1, erB = loHalf ? a2 : a3;

        int s0 = rp[w], s1 = rp[w + 1];
        float4 o0 = make_float4(0.f, 0.f, 0.f, 0.f);
        float4 o1 = make_float4(0.f, 0.f, 0.f, 0.f);
        if (s0 != s1) {
            float4 acc0 = make_float4(0.f, 0.f, 0.f, 0.f);
            float4 acc1 = make_float4(0.f, 0.f, 0.f, 0.f);
            float zA = 0.f, zB = 0.f;
            for (int j = s0; j < s1; j++) {
                int s = srcs[j];
                float4 e = el4[s];
                float eA = loHalf ? e.x : e.y, eB = loHalf ? e.z : e.w;
                float aA = __expf(lrelu(eA + erA, 0.2f));
                float aB = __expf(lrelu(eB + erB, 0.2f));
                const uint2* row = (const uint2*)(hs + (size_t)s * 256);
                uint2 q0 = row[lane];        // cols 4*lane..4*lane+3
                uint2 q1 = row[lane + 32];   // cols 128+4*lane..+3
                float2 p0 = __half22float2(*(const __half2*)&q0.x);
                float2 p1 = __half22float2(*(const __half2*)&q0.y);
                float2 p2 = __half22float2(*(const __half2*)&q1.x);
                float2 p3 = __half22float2(*(const __half2*)&q1.y);
                acc0.x += aA * p0.x; acc0.y += aA * p0.y;
                acc0.z += aA * p1.x; acc0.w += aA * p1.y;
                acc1.x += aB * p2.x; acc1.y += aB * p2.y;
                acc1.z += aB * p3.x; acc1.w += aB * p3.y;
                zA += aA; zB += aB;
            }
            float iA = 1.f / zA, iB = 1.f / zB;
            o0 = make_float4(acc0.x * iA, acc0.y * iA, acc0.z * iA, acc0.w * iA);
            o1 = make_float4(acc1.x * iB, acc1.y * iB, acc1.z * iB, acc1.w * iB);
        }
        float4* op = (float4*)(out + (size_t)w * 256);
        op[lane] = o0;
        op[lane + 32] = o1;
        sm0[0] += o0.x; sq0[0] += o0.x * o0.x;
        sm0[1] += o0.y; sq0[1] += o0.y * o0.y;
        sm0[2] += o0.z; sq0[2] += o0.z * o0.z;
        sm0[3] += o0.w; sq0[3] += o0.w * o0.w;
        sm1[0] += o1.x; sq1[0] += o1.x * o1.x;
        sm1[1] += o1.y; sq1[1] += o1.y * o1.y;
        sm1[2] += o1.z; sq1[2] += o1.z * o1.z;
        sm1[3] += o1.w; sq1[3] += o1.w * o1.w;
    }
    #pragma unroll
    for (int q = 0; q < 4; q++) {
        atomicAdd(&s_st[lane * 4 + q], sm0[q]);
        atomicAdd(&s_st[256 + lane * 4 + q], sq0[q]);
        atomicAdd(&s_st[128 + lane * 4 + q], sm1[q]);
        atomicAdd(&s_st[256 + 128 + lane * 4 + q], sq1[q]);
    }
    __syncthreads();
    for (int i = tid; i < 512; i += 256)
        atomicAdd(&stats[i], s_st[i]);
}

// ---- fused edge kernel, F=128 (dh=32): er + 1-pass softmax-agg; hs fp16 ----
__global__ void k_edge128f(const int* __restrict__ rp, const int* __restrict__ srcs,
                           const float4* __restrict__ el4, const float4* __restrict__ V4,
                           const float* __restrict__ cdst, const __half* __restrict__ hs,
                           float* __restrict__ out, int ndst, int fin) {
    int w = (blockIdx.x * blockDim.x + threadIdx.x) >> 5;
    int lane = threadIdx.x & 31;
    if (w >= ndst) return;
    const float* c = cdst + (size_t)w * fin;
    float a0 = 0.f, a1 = 0.f, a2 = 0.f, a3 = 0.f;
    for (int k = lane; k < fin; k += 32) {
        float xv = c[k];
        float4 v = V4[k];
        a0 += xv * v.x; a1 += xv * v.y; a2 += xv * v.z; a3 += xv * v.w;
    }
    #pragma unroll
    for (int o = 16; o; o >>= 1) {
        a0 += __shfl_xor_sync(0xffffffffu, a0, o);
        a1 += __shfl_xor_sync(0xffffffffu, a1, o);
        a2 += __shfl_xor_sync(0xffffffffu, a2, o);
        a3 += __shfl_xor_sync(0xffffffffu, a3, o);
    }
    int hsel = lane >> 3;
    float erS = (hsel == 0) ? a0 : (hsel == 1) ? a1 : (hsel == 2) ? a2 : a3;

    int s0 = rp[w], s1 = rp[w + 1];
    float4* o = (float4*)(out + (size_t)w * 128);
    if (s0 == s1) {
        o[lane] = make_float4(0.f, 0.f, 0.f, 0.f);
        return;
    }
    float4 acc = make_float4(0.f, 0.f, 0.f, 0.f);
    float z = 0.f;
    for (int j = s0; j < s1; j++) {
        int s = srcs[j];
        float4 e = el4[s];
        float eS = (hsel == 0) ? e.x : (hsel == 1) ? e.y : (hsel == 2) ? e.z : e.w;
        float a = __expf(lrelu(eS + erS, 0.2f));
        const uint2* row = (const uint2*)(hs + (size_t)s * 128);
        uint2 q = row[lane];
        float2 p0 = __half22float2(*(const __half2*)&q.x);
        float2 p1 = __half22float2(*(const __half2*)&q.y);
        acc.x += a * p0.x; acc.y += a * p0.y;
        acc.z += a * p1.x; acc.w += a * p1.y;
        z += a;
    }
    float iz = 1.f / z;
    o[lane] = make_float4(acc.x * iz, acc.y * iz, acc.z * iz, acc.w * iz);
}

// ------- BN apply (+act +bf16 split), 2 columns/thread, packed stores -------
__global__ void k_bnapply(const float* __restrict__ x, float* __restrict__ y,
                          uint32_t* __restrict__ yh, uint32_t* __restrict__ yl,
                          const float* __restrict__ bn, const float* __restrict__ stats,
                          int L, int n, int use_tanh) {
    int tid = threadIdx.x;
    int cp = (tid & 127) * 2;
    int rh = tid >> 7;
    float inv_n = 1.f / (float)n;
    float mu0 = stats[cp] * inv_n;
    float mu1 = stats[cp + 1] * inv_n;
    float var0 = stats[256 + cp] * inv_n - mu0 * mu0;
    float var1 = stats[256 + cp + 1] * inv_n - mu1 * mu1;
    float g0 = bn[(L * 2 + 0) * 256 + cp], g1 = bn[(L * 2 + 0) * 256 + cp + 1];
    float b0 = bn[(L * 2 + 1) * 256 + cp], b1 = bn[(L * 2 + 1) * 256 + cp + 1];
    float sc0 = g0 * rsqrtf(var0 + 1e-5f), sc1 = g1 * rsqrtf(var1 + 1e-5f);
    float sh0 = b0 - mu0 * sc0, sh1 = b1 - mu1 * sc1;
    for (int r = blockIdx.x * 2 + rh; r < n; r += gridDim.x * 2) {
        size_t idx = (size_t)r * 256 + cp;
        float2 v = *(const float2*)(x + idx);
        float v0 = sc0 * v.x + sh0;
        float v1 = sc1 * v.y + sh1;
        if (use_tanh) { v0 = fast_tanh(v0); v1 = fast_tanh(v1); }
        else {
            v0 = v0 > 0.f ? v0 : 0.01f * v0;
            v1 = v1 > 0.f ? v1 : 0.01f * v1;
        }
        *(float2*)(y + idx) = make_float2(v0, v1);
        float h0 = __bfloat162float(__float2bfloat16_rn(v0));
        float h1 = __bfloat162float(__float2bfloat16_rn(v1));
        yh[idx >> 1] = pack_bf16x2(v0, v1);
        yl[idx >> 1] = pack_bf16x2(v0 - h0, v1 - h1);
    }
}

// ---------------- static stream/event setup (pre-checkpoint) ----------------
namespace {
struct StreamInit {
    cudaStream_t s2 = 0;
    cudaEvent_t ev[32];
    bool ok = false;
    StreamInit() {
        if (cudaStreamCreateWithFlags(&s2, cudaStreamNonBlocking) != cudaSuccess) return;
        for (int i = 0; i < 32; i++)
            if (cudaEventCreateWithFlags(&ev[i], cudaEventDisableTiming) != cudaSuccess)
                return;
        k_noop<<<1, 32>>>();
        k_noop<<<1, 32, 0, s2>>>();
        for (int i = 0; i < 32; i++) cudaEventRecord(ev[i], (i & 1) ? s2 : 0);
        if (cudaDeviceSynchronize() != cudaSuccess) return;
        if (cudaGetLastError() != cudaSuccess) return;
        ok = true;
    }
};
StreamInit g_si;
}

// ---------------- host orchestration ----------------
static inline int wgrid(int nwarp) { return (nwarp * 32 + 255) / 256; }

struct Ptrs {
    float *hu, *hi, *nu, *ni;
    __half *hsu, *hsi;
    float *el_u, *el_i, *Vui, *Viu, *stats_i, *stats_u;
    __nv_bfloat16 *WHu, *WLu, *WHi, *WLi, *Auh, *Aul, *Aih, *Ail;
    int *rp_i, *rp_u, *srcs_i, *srcs_u, *cur_i, *cur_u, *part;
};

static void get_ptrs(Ptrs& p) {
    cudaGetSymbolAddress((void**)&p.hu, g_hu);
    cudaGetSymbolAddress((void**)&p.hi, g_hi);
    cudaGetSymbolAddress((void**)&p.hsu, g_hsu);
    cudaGetSymbolAddress((void**)&p.hsi, g_hsi);
    cudaGetSymbolAddress((void**)&p.nu, g_nu);
    cudaGetSymbolAddress((void**)&p.ni, g_ni);
    cudaGetSymbolAddress((void**)&p.el_u, g_el_u);
    cudaGetSymbolAddress((void**)&p.el_i, g_el_i);
    cudaGetSymbolAddress((void**)&p.Vui, g_Vui);
    cudaGetSymbolAddress((void**)&p.Viu, g_Viu);
    cudaGetSymbolAddress((void**)&p.stats_i, g_stats_i);
    cudaGetSymbolAddress((void**)&p.stats_u, g_stats_u);
    cudaGetSymbolAddress((void**)&p.WHu, g_WHu);
    cudaGetSymbolAddress((void**)&p.WLu, g_WLu);
    cudaGetSymbolAddress((void**)&p.WHi, g_WHi);
    cudaGetSymbolAddress((void**)&p.WLi, g_WLi);
    cudaGetSymbolAddress((void**)&p.Auh, g_Auh);
    cudaGetSymbolAddress((void**)&p.Aul, g_Aul);
    cudaGetSymbolAddress((void**)&p.Aih, g_Aih);
    cudaGetSymbolAddress((void**)&p.Ail, g_Ail);
    cudaGetSymbolAddress((void**)&p.rp_i, g_rp_i);
    cudaGetSymbolAddress((void**)&p.rp_u, g_rp_u);
    cudaGetSymbolAddress((void**)&p.srcs_i, g_srcs_i);
    cudaGetSymbolAddress((void**)&p.srcs_u, g_srcs_u);
    cudaGetSymbolAddress((void**)&p.cur_i, g_cur_i);
    cudaGetSymbolAddress((void**)&p.cur_u, g_cur_u);
    cudaGetSymbolAddress((void**)&p.part, g_part);
}

#define SMEM256 (2 * (2 * 128 * 80 + 2 * 32 * (256 * 2 + 16)))
#define SMEM128 (2 * (2 * 128 * 80 + 2 * 32 * (128 * 2 + 16)))
#define EDGE_BLOCKS 592

static const int WOFF[4] = {0, 32768, 98304, 163840};
static const int WSZ[4]  = {32768, 65536, 65536, 32768};
#define VOFF(L) ((L) * FHID * NHEAD)

static void scan(const int* cnt, int n, int* rp, int* part, cudaStream_t st) {
    int nb = (n + 1023) / 1024;
    k_scan_blk<<<nb, 1024, 0, st>>>(cnt, n, rp, part);
    k_scan_part<<<1, 64, 0, st>>>(part, nb);
    k_scan_add<<<nb, 1024, 0, st>>>(rp, part, n);
}

static void split4(const float* X, __nv_bfloat16* xh, __nv_bfloat16* xl, int total,
                   cudaStream_t st) {
    int t4 = total >> 2;
    k_split4<<<(t4 + 255) / 256, 256, 0, st>>>((const float4*)X, (uint2*)xh,
                                               (uint2*)xl, t4);
}

extern "C" void kernel_launch(void* const* d_in, const int* in_sizes, int n_in,
                              void* d_out, int out_size) {
    Ptrs p;
    get_ptrs(p);
    cudaFuncSetAttribute(k_mma_gemm<256, 64>,
                         cudaFuncAttributeMaxDynamicSharedMemorySize, SMEM256);
    cudaFuncSetAttribute(k_mma_gemm<128, 32>,
                         cudaFuncAttributeMaxDynamicSharedMemorySize, SMEM128);

    const float* x_user = (const float*)d_in[0];
    const float* x_item = (const float*)d_in[1];
    const int*   eu     = (const int*)d_in[2];
    const int*   ei     = (const int*)d_in[3];

    bool dictOrder = (in_sizes[5] < 10000);
    const float *Wui[4], *Aui[4], *Wiu[4], *Aiu[4];
    for (int L = 0; L < 4; L++) {
        if (dictOrder) {
            Wui[L] = (const float*)d_in[4 + L * 4 + 0];
            Aui[L] = (const float*)d_in[4 + L * 4 + 1];
            Wiu[L] = (const float*)d_in[4 + L * 4 + 2];
            Aiu[L] = (const float*)d_in[4 + L * 4 + 3];
        } else {
            Wui[L] = (const float*)d_in[4 + L * 4 + 0];
            Wiu[L] = (const float*)d_in[4 + L * 4 + 1];
            Aui[L] = (const float*)d_in[4 + L * 4 + 2];
            Aiu[L] = (const float*)d_in[4 + L * 4 + 3];
        }
    }
    const float* bn_u = (const float*)d_in[20];
    const float* bn_i = (const float*)d_in[21];
    float* out = (float*)d_out;

    cudaStream_t SA = 0;
    cudaStream_t SB = g_si.ok ? g_si.s2 : (cudaStream_t)0;
    bool fork = g_si.ok;
    int ec = 0;
    auto REC = [&](cudaStream_t st) -> int {
        if (!fork) return -1;
        int i = ec++;
        cudaEventRecord(g_si.ev[i], st);
        return i;
    };
    auto WAITE = [&](cudaStream_t st, int i) {
        if (fork && i >= 0) cudaStreamWaitEvent(st, g_si.ev[i], 0);
    };

    // ---- capture-legal fork ----
    int evFork = REC(SA);
    WAITE(SB, evFork);

    // ---- SA prologue ----
    k_zerof<<<6, 256, 0, SA>>>(p.stats_i, 3 * 512);
    split4(x_user, p.Auh, p.Aul, NUSR * FIN0, SA);
    split4(Wui[0], p.WHu + WOFF[0], p.WLu + WOFF[0], WSZ[0], SA);

    // ---- SB prologue ----
    split4(x_item, p.Aih, p.Ail, NITM * FIN0, SB);
    k_zeroi<<<(NUSR + 255) / 256, 256, 0, SB>>>(p.cur_u, NUSR);
    k_zeroi<<<(NITM + 255) / 256, 256, 0, SB>>>(p.cur_i, NITM);
    k_count<<<(NEDG + 255) / 256, 256, 0, SB>>>(eu, ei, p.cur_u, p.cur_i);
    scan(p.cur_i, NITM, p.rp_i, p.part, SB);
    scan(p.cur_u, NUSR, p.rp_u, p.part, SB);
    k_copyi<<<(NITM + 255) / 256, 256, 0, SB>>>(p.rp_i, p.cur_i, NITM);
    k_copyi<<<(NUSR + 255) / 256, 256, 0, SB>>>(p.rp_u, p.cur_u, NUSR);
    k_scatter<<<(NEDG + 255) / 256, 256, 0, SB>>>(eu, ei, p.cur_u, p.cur_i,
                                                  p.srcs_u, p.srcs_i);
    {
        CVArgs cva;
        for (int L = 0; L < 4; L++) {
            cva.W[L] = Wui[L];  cva.A[L] = Aui[L];
            cva.W[4 + L] = Wiu[L];  cva.A[4 + L] = Aiu[L];
        }
        k_collapseAll<<<28, 256, 0, SB>>>(cva, p.Vui, p.Viu);
    }
    int evPre = REC(SB);
    k_zerof<<<6, 256, 0, SB>>>(p.stats_u, 3 * 512);
    split4(Wiu[0], p.WHi + WOFF[0], p.WLi + WOFF[0], WSZ[0], SB);

    const float* cu = x_user;
    const float* ci = x_item;
    int fin = FIN0;
    for (int L = 0; L < 4; L++) {
        int F = (L == 3) ? 128 : 256;
        float* outi = (L == 3) ? (out + (size_t)NUSR * 128) : p.ni;
        float* outu = (L == 3) ? out : p.nu;
        int gbU = (NUSR + 127) / 128, gbI = (NITM + 127) / 128;

        // ---- SA: user GEMM (+el_u) ----
        if (F == 256)
            k_mma_gemm<256, 64><<<gbU, 512, SMEM256, SA>>>(p.Auh, p.Aul,
                p.WHu + WOFF[L], p.WLu + WOFF[L], Aui[L], p.hsu, p.el_u, NUSR, fin);
        else
            k_mma_gemm<128, 32><<<gbU, 256, SMEM128, SA>>>(p.Auh, p.Aul,
                p.WHu + WOFF[L], p.WLu + WOFF[L], Aui[L], p.hsu, p.el_u, NUSR, fin);
        int evAg = REC(SA);

        // ---- SB: item GEMM (+el_i) ----
        if (F == 256)
            k_mma_gemm<256, 64><<<gbI, 512, SMEM256, SB>>>(p.Aih, p.Ail,
                p.WHi + WOFF[L], p.WLi + WOFF[L], Aiu[L], p.hsi, p.el_i, NITM, fin);
        else
            k_mma_gemm<128, 32><<<gbI, 256, SMEM128, SB>>>(p.Aih, p.Ail,
                p.WHi + WOFF[L], p.WLi + WOFF[L], Aiu[L], p.hsi, p.el_i, NITM, fin);
        int evBg = REC(SB);

        // ---- deferred weight splits for L1..3 ----
        if (L == 0) {
            for (int l = 1; l < 4; l++) {
                split4(Wui[l], p.WHu + WOFF[l], p.WLu + WOFF[l], WSZ[l], SA);
                split4(Wiu[l], p.WHi + WOFF[l], p.WLi + WOFF[l], WSZ[l], SB);
            }
        }

        // ---- fused edges ----
        if (L == 0) WAITE(SA, evPre);
        if (F == 256) {
            k_edge256s<<<EDGE_BLOCKS, 256, 0, SA>>>(p.rp_i, p.srcs_i,
                (const float4*)p.el_u, (const float4*)(p.Vui + VOFF(L)), ci,
                p.hsu, outi, p.stats_i + L * 512, NITM, fin);
            k_edge256s<<<EDGE_BLOCKS, 256, 0, SB>>>(p.rp_u, p.srcs_u,
                (const float4*)p.el_i, (const float4*)(p.Viu + VOFF(L)), cu,
                p.hsi, outu, p.stats_u + L * 512, NUSR, fin);
        } else {
            k_edge128f<<<wgrid(NITM), 256, 0, SA>>>(p.rp_i, p.srcs_i,
                (const float4*)p.el_u, (const float4*)(p.Vui + VOFF(L)), ci,
                p.hsu, outi, NITM, fin);
            k_edge128f<<<wgrid(NUSR), 256, 0, SB>>>(p.rp_u, p.srcs_u,
                (const float4*)p.el_i, (const float4*)(p.Viu + VOFF(L)), cu,
                p.hsi, outu, NUSR, fin);
        }

        if (L < 3) {
            WAITE(SA, evBg);
            k_bnapply<<<256, 256, 0, SA>>>(p.ni, p.hi, (uint32_t*)p.Aih,
                                           (uint32_t*)p.Ail, bn_i,
                                           p.stats_i + L * 512, L, NITM,
                                           (L == 2) ? 1 : 0);
            WAITE(SB, evAg);
            k_bnapply<<<256, 256, 0, SB>>>(p.nu, p.hu, (uint32_t*)p.Auh,
                                           (uint32_t*)p.Aul, bn_u,
                                           p.stats_u + L * 512, L, NUSR,
                                           (L == 2) ? 1 : 0);
            int evAe = REC(SA);
            int evBe = REC(SB);
            WAITE(SA, evBe);
            WAITE(SB, evAe);
            cu = p.hu;
            ci = p.hi;
            fin = FHID;
        } else {
            int evBf = REC(SB);
            WAITE(SA, evBf);
        }
    }
    (void)n_in; (void)out_size;
}

// round 13
// speedup vs baseline: 1.0067x; 1.0067x over previous
#include <cuda_runtime.h>
#include <cuda_bf16.h>
#include <math.h>
#include <stddef.h>
#include <stdint.h>

// ---------------- problem constants ----------------
#define NUSR 50000
#define NITM 20000
#define NEDG 400000
#define FIN0 128
#define FHID 256
#define NHEAD 4

// ---------------- device scratch (no allocs allowed) ----------------
__device__ float g_hu [(size_t)NUSR * FHID];
__device__ float g_hi [(size_t)NITM * FHID];
__device__ float g_hsu[(size_t)NUSR * FHID];
__device__ float g_hsi[(size_t)NITM * FHID];
__device__ float g_nu [(size_t)NUSR * FHID];
__device__ float g_ni [(size_t)NITM * FHID];
__device__ float g_el_u[NUSR * 4];
__device__ float g_el_i[NITM * 4];
__device__ int   g_rp_i[NITM + 1];
__device__ int   g_rp_u[NUSR + 1];
__device__ int   g_srcs_i[NEDG];
__device__ int   g_srcs_u[NEDG];
__device__ int   g_cur_i[NITM];
__device__ int   g_cur_u[NUSR];
__device__ float g_Vui[4 * FHID * NHEAD];
__device__ float g_Viu[4 * FHID * NHEAD];
__device__ float g_stats_i[3 * 512];
__device__ float g_stats_u[3 * 512];
__device__ int   g_part[64];
__device__ __nv_bfloat16 g_WHu[196608];
__device__ __nv_bfloat16 g_WLu[196608];
__device__ __nv_bfloat16 g_WHi[196608];
__device__ __nv_bfloat16 g_WLi[196608];
__device__ __nv_bfloat16 g_Auh[(size_t)NUSR * FHID];
__device__ __nv_bfloat16 g_Aul[(size_t)NUSR * FHID];
__device__ __nv_bfloat16 g_Aih[(size_t)NITM * FHID];
__device__ __nv_bfloat16 g_Ail[(size_t)NITM * FHID];

// ---------------- PTX helpers (baseline features only) ----------------
__device__ __forceinline__ uint32_t smem_u32(const void* p) {
    uint32_t a;
    asm("{ .reg .u64 t; cvta.to.shared.u64 t, %1; cvt.u32.u64 %0, t; }"
        : "=r"(a) : "l"(p));
    return a;
}
__device__ __forceinline__ void ldsm4(uint32_t* r, uint32_t addr) {
    asm volatile("ldmatrix.sync.aligned.m8n8.x4.shared.b16 {%0,%1,%2,%3}, [%4];"
        : "=r"(r[0]), "=r"(r[1]), "=r"(r[2]), "=r"(r[3]) : "r"(addr));
}
__device__ __forceinline__ void ldsm4t(uint32_t* r, uint32_t addr) {
    asm volatile("ldmatrix.sync.aligned.m8n8.x4.trans.shared.b16 {%0,%1,%2,%3}, [%4];"
        : "=r"(r[0]), "=r"(r[1]), "=r"(r[2]), "=r"(r[3]) : "r"(addr));
}
__device__ __forceinline__ void mma16816(float* c, const uint32_t* a,
                                         uint32_t b0, uint32_t b1) {
    asm volatile(
        "mma.sync.aligned.m16n8k16.row.col.f32.bf16.bf16.f32 "
        "{%0,%1,%2,%3}, {%4,%5,%6,%7}, {%8,%9}, {%0,%1,%2,%3};"
        : "+f"(c[0]), "+f"(c[1]), "+f"(c[2]), "+f"(c[3])
        : "r"(a[0]), "r"(a[1]), "r"(a[2]), "r"(a[3]), "r"(b0), "r"(b1));
}
#define CPA16(dst, src) \
    asm volatile("cp.async.cg.shared.global [%0], [%1], 16;" \
                 :: "r"(dst), "l"(src))
#define CP_COMMIT() asm volatile("cp.async.commit_group;")
#define CP_WAIT1()  asm volatile("cp.async.wait_group 1;" ::: "memory")
#define CP_WAIT0()  asm volatile("cp.async.wait_group 0;" ::: "memory")

__device__ __forceinline__ uint32_t pack_bf16x2(float a, float b) {
    return ((uint32_t)__bfloat16_as_ushort(__float2bfloat16_rn(b)) << 16) |
           __bfloat16_as_ushort(__float2bfloat16_rn(a));
}
__device__ __forceinline__ float fast_tanh(float x) {
    x = fminf(fmaxf(x, -15.f), 15.f);
    float e = __expf(2.f * x);
    return (e - 1.f) / (e + 1.f);
}

// ---------------- tiny utility kernels ----------------
__global__ void k_noop() {}
__global__ void k_zeroi(int* p, int n) {
    int i = blockIdx.x * blockDim.x + threadIdx.x;
    if (i < n) p[i] = 0;
}
__global__ void k_zerof(float* p, int n) {
    int i = blockIdx.x * blockDim.x + threadIdx.x;
    if (i < n) p[i] = 0.f;
}
__global__ void k_copyi(const int* __restrict__ a, int* __restrict__ b, int n) {
    int i = blockIdx.x * blockDim.x + threadIdx.x;
    if (i < n) b[i] = a[i];
}

// ---------------- CSR construction ----------------
__global__ void k_count(const int* __restrict__ eu, const int* __restrict__ ei,
                        int* cu, int* ci) {
    int k = blockIdx.x * blockDim.x + threadIdx.x;
    if (k < NEDG) {
        atomicAdd(&ci[ei[k]], 1);
        atomicAdd(&cu[eu[k]], 1);
    }
}
__global__ void k_scan_blk(const int* __restrict__ cnt, int n,
                           int* __restrict__ rp, int* __restrict__ part) {
    __shared__ int ws[32];
    int tid = threadIdx.x;
    int i = blockIdx.x * 1024 + tid;
    int v = (i < n) ? cnt[i] : 0;
    int lane = tid & 31, w = tid >> 5;
    int x = v;
    #pragma unroll
    for (int o = 1; o < 32; o <<= 1) {
        int y = __shfl_up_sync(0xffffffffu, x, o);
        if (lane >= o) x += y;
    }
    if (lane == 31) ws[w] = x;
    __syncthreads();
    if (w == 0) {
        int t = ws[lane];
        #pragma unroll
        for (int o = 1; o < 32; o <<= 1) {
            int y = __shfl_up_sync(0xffffffffu, t, o);
            if (lane >= o) t += y;
        }
        ws[lane] = t;
    }
    __syncthreads();
    int incl = x + (w > 0 ? ws[w - 1] : 0);
    if (i < n) rp[i + 1] = incl;
    if (tid == 1023) part[blockIdx.x] = incl;
}
__global__ void k_scan_part(int* part, int nb) {
    __shared__ int w0sum;
    int tid = threadIdx.x;
    int v = (tid < nb) ? part[tid] : 0;
    int lane = tid & 31, w = tid >> 5;
    int x = v;
    #pragma unroll
    for (int o = 1; o < 32; o <<= 1) {
        int y = __shfl_up_sync(0xffffffffu, x, o);
        if (lane >= o) x += y;
    }
    if (w == 0 && lane == 31) w0sum = x;
    __syncthreads();
    int incl = x + (w ? w0sum : 0);
    if (tid < nb) part[tid] = incl - v;
}
__global__ void k_scan_add(int* __restrict__ rp, const int* __restrict__ part, int n) {
    int i = blockIdx.x * 1024 + threadIdx.x;
    if (i < n) rp[i + 1] += part[blockIdx.x];
    if (i == 0) rp[0] = 0;
}
__global__ void k_scatter(const int* __restrict__ eu, const int* __restrict__ ei,
                          int* cu, int* ci,
                          int* __restrict__ su, int* __restrict__ si) {
    int k = blockIdx.x * blockDim.x + threadIdx.x;
    if (k < NEDG) {
        int u = eu[k], it = ei[k];
        int p = atomicAdd(&ci[it], 1);
        si[p] = u;
        int q = atomicAdd(&cu[u], 1);
        su[q] = it;
    }
}

// ------- vectorized fp32 -> bf16 hi/lo split: 4 elems per thread -------
__global__ void k_split4(const float4* __restrict__ X, uint2* __restrict__ xh,
                         uint2* __restrict__ xl, int total4) {
    int id = blockIdx.x * blockDim.x + threadIdx.x;
    if (id >= total4) return;
    float4 v = X[id];
    float hx = __bfloat162float(__float2bfloat16_rn(v.x));
    float hy = __bfloat162float(__float2bfloat16_rn(v.y));
    float hz = __bfloat162float(__float2bfloat16_rn(v.z));
    float hw = __bfloat162float(__float2bfloat16_rn(v.w));
    xh[id] = make_uint2(pack_bf16x2(v.x, v.y), pack_bf16x2(v.z, v.w));
    xl[id] = make_uint2(pack_bf16x2(v.x - hx, v.y - hy),
                        pack_bf16x2(v.z - hz, v.w - hw));
}

// ---------------- batched collapseV ----------------
struct CVArgs { const float* W[8]; const float* A[8]; };
__global__ void k_collapseAll(CVArgs a, float* __restrict__ Vui,
                              float* __restrict__ Viu) {
    int t = blockIdx.x * blockDim.x + threadIdx.x;
    if (t >= 7168) return;
    int side = (t >= 3584) ? 1 : 0;
    int u = t - side * 3584;
    int L, off;
    if (u < 512)       { L = 0; off = 0; }
    else if (u < 1536) { L = 1; off = 512; }
    else if (u < 2560) { L = 2; off = 1536; }
    else               { L = 3; off = 2560; }
    int local = u - off;
    int k = local >> 2, h = local & 3;
    int F = (L == 3) ? 128 : 256;
    int dh = (L == 3) ? 32 : 64;
    const float* W = a.W[side * 4 + L];
    const float* A1 = a.A[side * 4 + L] + NHEAD * dh;
    float s = 0.f;
    for (int d = 0; d < dh; d++)
        s += W[(size_t)k * F + h * dh + d] * A1[h * dh + d];
    (side ? Viu : Vui)[L * FHID * NHEAD + local] = s;
}

// ---------------- tensor-core GEMM + fused el epilogue ----------------
template <int BN, int DH>
__global__ void __launch_bounds__((BN == 256) ? 512 : 256, 1)
k_mma_gemm(const __nv_bfloat16* __restrict__ Ah, const __nv_bfloat16* __restrict__ Al,
           const __nv_bfloat16* __restrict__ Bh, const __nv_bfloat16* __restrict__ Bl,
           const float* __restrict__ attA,
           float* __restrict__ C, float* __restrict__ el, int M, int K) {
    constexpr int NT = (BN == 256) ? 512 : 256;
    constexpr int SBSTR = BN * 2 + 16;
    constexpr int ASZ = 128 * 80;
    constexpr int BOFF = 2 * ASZ;
    constexpr int BSZ = 32 * SBSTR;
    constexpr int STAGE = BOFF + 2 * BSZ;
    constexpr int NBC = 32 * (BN / 8);

    extern __shared__ char smem[];
    uint32_t sb = smem_u32(smem);
    int tid = threadIdx.x;
    int wid = tid >> 5, lane = tid & 31;
    int wm = wid & 3, wn = wid >> 2;
    int bm = blockIdx.x * 128;

    float acc[2][8][4];
    #pragma unroll
    for (int i = 0; i < 2; i++)
        #pragma unroll
        for (int j = 0; j < 8; j++)
            #pragma unroll
            for (int q = 0; q < 4; q++) acc[i][j][q] = 0.f;

    int nch = K >> 5;

    auto load_stage = [&](int st, int kc) {
        uint32_t sbase = sb + st * STAGE;
        int k0 = kc << 5;
        #pragma unroll
        for (int c = tid; c < 512; c += NT) {
            int row = c >> 2, q = c & 3;
            int gr = bm + row;
            gr = gr < M ? gr : M - 1;
            size_t gi = (size_t)gr * K + k0 + q * 8;
            uint32_t d = sbase + row * 80 + q * 16;
            CPA16(d, Ah + gi);
            CPA16(d + ASZ, Al + gi);
        }
        #pragma unroll
        for (int c = tid; c < NBC; c += NT) {
            int k = c / (BN / 8), seg = c % (BN / 8);
            size_t gi = (size_t)(k0 + k) * BN + seg * 8;
            uint32_t d = sbase + BOFF + k * SBSTR + seg * 16;
            CPA16(d, Bh + gi);
            CPA16(d + BSZ, Bl + gi);
        }
        CP_COMMIT();
    };

    load_stage(0, 0);
    for (int kc = 0; kc < nch; kc++) {
        int cur = kc & 1;
        if (kc + 1 < nch) {
            load_stage(1 - cur, kc + 1);
            CP_WAIT1();
        } else {
            CP_WAIT0();
        }
        __syncthreads();
        uint32_t abase = sb + cur * STAGE;
        #pragma unroll
        for (int s = 0; s < 2; s++) {
            uint32_t Af[2][4], Alf[2][4];
            #pragma unroll
            for (int mt = 0; mt < 2; mt++) {
                uint32_t ad = abase +
                    (uint32_t)(wm * 32 + mt * 16 + (lane & 15)) * 80 +
                    s * 32 + (lane >> 4) * 16;
                ldsm4(Af[mt], ad);
                ldsm4(Alf[mt], ad + ASZ);
            }
            #pragma unroll
            for (int np = 0; np < 4; np++) {
                int g = lane >> 3, r = lane & 7;
                int kk = s * 16 + (g & 1) * 8 + r;
                int nn = wn * 64 + np * 16 + (g >> 1) * 8;
                uint32_t bd = abase + BOFF + (uint32_t)kk * SBSTR + nn * 2;
                uint32_t bh4[4], bl4[4];
                ldsm4t(bh4, bd);
                ldsm4t(bl4, bd + BSZ);
                #pragma unroll
                for (int mt = 0; mt < 2; mt++)
                    #pragma unroll
                    for (int sub = 0; sub < 2; sub++) {
                        float* a = acc[mt][np * 2 + sub];
                        mma16816(a, Af[mt], bh4[2 * sub], bh4[2 * sub + 1]);
                        mma16816(a, Af[mt], bl4[2 * sub], bl4[2 * sub + 1]);
                        mma16816(a, Alf[mt], bh4[2 * sub], bh4[2 * sub + 1]);
                    }
            }
        }
        __syncthreads();
    }

    constexpr int HPW = 64 / DH;
    int grp = lane >> 2, tq = lane & 3;
    #pragma unroll
    for (int mt = 0; mt < 2; mt++) {
        int r0 = bm + wm * 32 + mt * 16 + grp;
        int r1 = r0 + 8;
        #pragma unroll
        for (int nt = 0; nt < 8; nt++) {
            int col = wn * 64 + nt * 8 + tq * 2;
            if (r0 < M)
                *(float2*)(C + (size_t)r0 * BN + col) =
                    make_float2(acc[mt][nt][0], acc[mt][nt][1]);
            if (r1 < M)
                *(float2*)(C + (size_t)r1 * BN + col) =
                    make_float2(acc[mt][nt][2], acc[mt][nt][3]);
        }
        float s0[HPW], s1[HPW];
        #pragma unroll
        for (int p = 0; p < HPW; p++) { s0[p] = 0.f; s1[p] = 0.f; }
        #pragma unroll
        for (int nt = 0; nt < 8; nt++) {
            int part = (nt * 8) / DH;
            int col = wn * 64 + nt * 8 + tq * 2;
            float c0 = attA[col], c1 = attA[col + 1];
            s0[part] += c0 * acc[mt][nt][0] + c1 * acc[mt][nt][1];
            s1[part] += c0 * acc[mt][nt][2] + c1 * acc[mt][nt][3];
        }
        #pragma unroll
        for (int p = 0; p < HPW; p++) {
            s0[p] += __shfl_xor_sync(0xffffffffu, s0[p], 1);
            s0[p] += __shfl_xor_sync(0xffffffffu, s0[p], 2);
            s1[p] += __shfl_xor_sync(0xffffffffu, s1[p], 1);
            s1[p] += __shfl_xor_sync(0xffffffffu, s1[p], 2);
            if (tq == 0) {
                int h = wn * HPW + p;
                if (r0 < M) el[r0 * 4 + h] = s0[p];
                if (r1 < M) el[r1 * 4 + h] = s1[p];
            }
        }
    }
}

__device__ __forceinline__ float lrelu(float x, float s) { return x > 0.f ? x : s * x; }

// ---- fused edge kernel, F=256: er + 1-pass softmax-agg + BN stats ----
// gather loop unrolled x2 for memory-level parallelism
__global__ void __launch_bounds__(256)
k_edge256s(const int* __restrict__ rp, const int* __restrict__ srcs,
           const float4* __restrict__ el4, const float4* __restrict__ V4,
           const float* __restrict__ cdst, const float* __restrict__ hs,
           float* __restrict__ out, float* __restrict__ stats,
           int ndst, int fin) {
    __shared__ float s_st[512];
    int tid = threadIdx.x;
    for (int i = tid; i < 512; i += 256) s_st[i] = 0.f;
    __syncthreads();
    int lane = tid & 31, wloc = tid >> 5;
    bool loHalf = lane < 16;
    float sm0[4] = {0.f, 0.f, 0.f, 0.f}, sq0[4] = {0.f, 0.f, 0.f, 0.f};
    float sm1[4] = {0.f, 0.f, 0.f, 0.f}, sq1[4] = {0.f, 0.f, 0.f, 0.f};

    for (int w = blockIdx.x * 8 + wloc; w < ndst; w += gridDim.x * 8) {
        const float* c = cdst + (size_t)w * fin;
        float a0 = 0.f, a1 = 0.f, a2 = 0.f, a3 = 0.f;
        for (int k = lane; k < fin; k += 32) {
            float xv = c[k];
            float4 v = V4[k];
            a0 += xv * v.x; a1 += xv * v.y; a2 += xv * v.z; a3 += xv * v.w;
        }
        #pragma unroll
        for (int o = 16; o; o >>= 1) {
            a0 += __shfl_xor_sync(0xffffffffu, a0, o);
            a1 += __shfl_xor_sync(0xffffffffu, a1, o);
            a2 += __shfl_xor_sync(0xffffffffu, a2, o);
            a3 += __shfl_xor_sync(0xffffffffu, a3, o);
        }
        float erA = loHalf ? a0 : a1, erB = loHalf ? a2 : a3;

        int s0 = rp[w], s1 = rp[w + 1];
        float4 o0 = make_float4(0.f, 0.f, 0.f, 0.f);
        float4 o1 = make_float4(0.f, 0.f, 0.f, 0.f);
        if (s0 != s1) {
            float4 acc0 = make_float4(0.f, 0.f, 0.f, 0.f);
            float4 acc1 = make_float4(0.f, 0.f, 0.f, 0.f);
            float zA = 0.f, zB = 0.f;
            int j = s0;
            for (; j + 1 < s1; j += 2) {
                int sX = srcs[j];
                int sY = srcs[j + 1];
                float4 eX = el4[sX];
                float4 eY = el4[sY];
                const float4* rowX = (const float4*)(hs + (size_t)sX * 256);
                const float4* rowY = (const float4*)(hs + (size_t)sY * 256);
                float4 vX0 = rowX[lane];
                float4 vX1 = rowX[lane + 32];
                float4 vY0 = rowY[lane];
                float4 vY1 = rowY[lane + 32];
                float eXA = loHalf ? eX.x : eX.y, eXB = loHalf ? eX.z : eX.w;
                float eYA = loHalf ? eY.x : eY.y, eYB = loHalf ? eY.z : eY.w;
                float aXA = __expf(lrelu(eXA + erA, 0.2f));
                float aXB = __expf(lrelu(eXB + erB, 0.2f));
                float aYA = __expf(lrelu(eYA + erA, 0.2f));
                float aYB = __expf(lrelu(eYB + erB, 0.2f));
                acc0.x += aXA * vX0.x + aYA * vY0.x;
                acc0.y += aXA * vX0.y + aYA * vY0.y;
                acc0.z += aXA * vX0.z + aYA * vY0.z;
                acc0.w += aXA * vX0.w + aYA * vY0.w;
                acc1.x += aXB * vX1.x + aYB * vY1.x;
                acc1.y += aXB * vX1.y + aYB * vY1.y;
                acc1.z += aXB * vX1.z + aYB * vY1.z;
                acc1.w += aXB * vX1.w + aYB * vY1.w;
                zA += aXA + aYA;
                zB += aXB + aYB;
            }
            if (j < s1) {
                int s = srcs[j];
                float4 e = el4[s];
                float eA = loHalf ? e.x : e.y, eB = loHalf ? e.z : e.w;
                float aA = __expf(lrelu(eA + erA, 0.2f));
                float aB = __expf(lrelu(eB + erB, 0.2f));
                const float4* row = (const float4*)(hs + (size_t)s * 256);
                float4 v0 = row[lane];
                float4 v1 = row[lane + 32];
                acc0.x += aA * v0.x; acc0.y += aA * v0.y;
                acc0.z += aA * v0.z; acc0.w += aA * v0.w;
                acc1.x += aB * v1.x; acc1.y += aB * v1.y;
                acc1.z += aB * v1.z; acc1.w += aB * v1.w;
                zA += aA; zB += aB;
            }
            float iA = 1.f / zA, iB = 1.f / zB;
            o0 = make_float4(acc0.x * iA, acc0.y * iA, acc0.z * iA, acc0.w * iA);
            o1 = make_float4(acc1.x * iB, acc1.y * iB, acc1.z * iB, acc1.w * iB);
        }
        float4* op = (float4*)(out + (size_t)w * 256);
        op[lane] = o0;
        op[lane + 32] = o1;
        sm0[0] += o0.x; sq0[0] += o0.x * o0.x;
        sm0[1] += o0.y; sq0[1] += o0.y * o0.y;
        sm0[2] += o0.z; sq0[2] += o0.z * o0.z;
        sm0[3] += o0.w; sq0[3] += o0.w * o0.w;
        sm1[0] += o1.x; sq1[0] += o1.x * o1.x;
        sm1[1] += o1.y; sq1[1] += o1.y * o1.y;
        sm1[2] += o1.z; sq1[2] += o1.z * o1.z;
        sm1[3] += o1.w; sq1[3] += o1.w * o1.w;
    }
    #pragma unroll
    for (int q = 0; q < 4; q++) {
        atomicAdd(&s_st[lane * 4 + q], sm0[q]);
        atomicAdd(&s_st[256 + lane * 4 + q], sq0[q]);
        atomicAdd(&s_st[128 + lane * 4 + q], sm1[q]);
        atomicAdd(&s_st[256 + 128 + lane * 4 + q], sq1[q]);
    }
    __syncthreads();
    for (int i = tid; i < 512; i += 256)
        atomicAdd(&stats[i], s_st[i]);
}

// ---- fused edge kernel, F=128 (dh=32): er + 1-pass softmax-agg, unrolled x2 ----
__global__ void k_edge128f(const int* __restrict__ rp, const int* __restrict__ srcs,
                           const float4* __restrict__ el4, const float4* __restrict__ V4,
                           const float* __restrict__ cdst, const float* __restrict__ hs,
                           float* __restrict__ out, int ndst, int fin) {
    int w = (blockIdx.x * blockDim.x + threadIdx.x) >> 5;
    int lane = threadIdx.x & 31;
    if (w >= ndst) return;
    const float* c = cdst + (size_t)w * fin;
    float a0 = 0.f, a1 = 0.f, a2 = 0.f, a3 = 0.f;
    for (int k = lane; k < fin; k += 32) {
        float xv = c[k];
        float4 v = V4[k];
        a0 += xv * v.x; a1 += xv * v.y; a2 += xv * v.z; a3 += xv * v.w;
    }
    #pragma unroll
    for (int o = 16; o; o >>= 1) {
        a0 += __shfl_xor_sync(0xffffffffu, a0, o);
        a1 += __shfl_xor_sync(0xffffffffu, a1, o);
        a2 += __shfl_xor_sync(0xffffffffu, a2, o);
        a3 += __shfl_xor_sync(0xffffffffu, a3, o);
    }
    int hsel = lane >> 3;
    float erS = (hsel == 0) ? a0 : (hsel == 1) ? a1 : (hsel == 2) ? a2 : a3;

    int s0 = rp[w], s1 = rp[w + 1];
    float4* o = (float4*)(out + (size_t)w * 128);
    if (s0 == s1) {
        o[lane] = make_float4(0.f, 0.f, 0.f, 0.f);
        return;
    }
    float4 acc = make_float4(0.f, 0.f, 0.f, 0.f);
    float z = 0.f;
    int j = s0;
    for (; j + 1 < s1; j += 2) {
        int sX = srcs[j];
        int sY = srcs[j + 1];
        float4 eX = el4[sX];
        float4 eY = el4[sY];
        const float4* rowX = (const float4*)(hs + (size_t)sX * 128);
        const float4* rowY = (const float4*)(hs + (size_t)sY * 128);
        float4 vX = rowX[lane];
        float4 vY = rowY[lane];
        float eXS = (hsel == 0) ? eX.x : (hsel == 1) ? eX.y : (hsel == 2) ? eX.z : eX.w;
        float eYS = (hsel == 0) ? eY.x : (hsel == 1) ? eY.y : (hsel == 2) ? eY.z : eY.w;
        float aX = __expf(lrelu(eXS + erS, 0.2f));
        float aY = __expf(lrelu(eYS + erS, 0.2f));
        acc.x += aX * vX.x + aY * vY.x;
        acc.y += aX * vX.y + aY * vY.y;
        acc.z += aX * vX.z + aY * vY.z;
        acc.w += aX * vX.w + aY * vY.w;
        z += aX + aY;
    }
    if (j < s1) {
        int s = srcs[j];
        float4 e = el4[s];
        float eS = (hsel == 0) ? e.x : (hsel == 1) ? e.y : (hsel == 2) ? e.z : e.w;
        float a = __expf(lrelu(eS + erS, 0.2f));
        const float4* row = (const float4*)(hs + (size_t)s * 128);
        float4 v = row[lane];
        acc.x += a * v.x; acc.y += a * v.y; acc.z += a * v.z; acc.w += a * v.w;
        z += a;
    }
    float iz = 1.f / z;
    o[lane] = make_float4(acc.x * iz, acc.y * iz, acc.z * iz, acc.w * iz);
}

// ------- BN apply (+act +bf16 split), 2 columns/thread, packed stores -------
__global__ void k_bnapply(const float* __restrict__ x, float* __restrict__ y,
                          uint32_t* __restrict__ yh, uint32_t* __restrict__ yl,
                          const float* __restrict__ bn, const float* __restrict__ stats,
                          int L, int n, int use_tanh) {
    int tid = threadIdx.x;
    int cp = (tid & 127) * 2;
    int rh = tid >> 7;
    float inv_n = 1.f / (float)n;
    float mu0 = stats[cp] * inv_n;
    float mu1 = stats[cp + 1] * inv_n;
    float var0 = stats[256 + cp] * inv_n - mu0 * mu0;
    float var1 = stats[256 + cp + 1] * inv_n - mu1 * mu1;
    float g0 = bn[(L * 2 + 0) * 256 + cp], g1 = bn[(L * 2 + 0) * 256 + cp + 1];
    float b0 = bn[(L * 2 + 1) * 256 + cp], b1 = bn[(L * 2 + 1) * 256 + cp + 1];
    float sc0 = g0 * rsqrtf(var0 + 1e-5f), sc1 = g1 * rsqrtf(var1 + 1e-5f);
    float sh0 = b0 - mu0 * sc0, sh1 = b1 - mu1 * sc1;
    for (int r = blockIdx.x * 2 + rh; r < n; r += gridDim.x * 2) {
        size_t idx = (size_t)r * 256 + cp;
        float2 v = *(const float2*)(x + idx);
        float v0 = sc0 * v.x + sh0;
        float v1 = sc1 * v.y + sh1;
        if (use_tanh) { v0 = fast_tanh(v0); v1 = fast_tanh(v1); }
        else {
            v0 = v0 > 0.f ? v0 : 0.01f * v0;
            v1 = v1 > 0.f ? v1 : 0.01f * v1;
        }
        *(float2*)(y + idx) = make_float2(v0, v1);
        float h0 = __bfloat162float(__float2bfloat16_rn(v0));
        float h1 = __bfloat162float(__float2bfloat16_rn(v1));
        yh[idx >> 1] = pack_bf16x2(v0, v1);
        yl[idx >> 1] = pack_bf16x2(v0 - h0, v1 - h1);
    }
}

// ---------------- static stream/event setup (pre-checkpoint) ----------------
namespace {
struct StreamInit {
    cudaStream_t s2 = 0;
    cudaEvent_t ev[32];
    bool ok = false;
    StreamInit() {
        if (cudaStreamCreateWithFlags(&s2, cudaStreamNonBlocking) != cudaSuccess) return;
        for (int i = 0; i < 32; i++)
            if (cudaEventCreateWithFlags(&ev[i], cudaEventDisableTiming) != cudaSuccess)
                return;
        k_noop<<<1, 32>>>();
        k_noop<<<1, 32, 0, s2>>>();
        for (int i = 0; i < 32; i++) cudaEventRecord(ev[i], (i & 1) ? s2 : 0);
        if (cudaDeviceSynchronize() != cudaSuccess) return;
        if (cudaGetLastError() != cudaSuccess) return;
        ok = true;
    }
};
StreamInit g_si;
}

// ---------------- host orchestration ----------------
static inline int wgrid(int nwarp) { return (nwarp * 32 + 255) / 256; }

struct Ptrs {
    float *hu, *hi, *hsu, *hsi, *nu, *ni;
    float *el_u, *el_i, *Vui, *Viu, *stats_i, *stats_u;
    __nv_bfloat16 *WHu, *WLu, *WHi, *WLi, *Auh, *Aul, *Aih, *Ail;
    int *rp_i, *rp_u, *srcs_i, *srcs_u, *cur_i, *cur_u, *part;
};

static void get_ptrs(Ptrs& p) {
    cudaGetSymbolAddress((void**)&p.hu, g_hu);
    cudaGetSymbolAddress((void**)&p.hi, g_hi);
    cudaGetSymbolAddress((void**)&p.hsu, g_hsu);
    cudaGetSymbolAddress((void**)&p.hsi, g_hsi);
    cudaGetSymbolAddress((void**)&p.nu, g_nu);
    cudaGetSymbolAddress((void**)&p.ni, g_ni);
    cudaGetSymbolAddress((void**)&p.el_u, g_el_u);
    cudaGetSymbolAddress((void**)&p.el_i, g_el_i);
    cudaGetSymbolAddress((void**)&p.Vui, g_Vui);
    cudaGetSymbolAddress((void**)&p.Viu, g_Viu);
    cudaGetSymbolAddress((void**)&p.stats_i, g_stats_i);
    cudaGetSymbolAddress((void**)&p.stats_u, g_stats_u);
    cudaGetSymbolAddress((void**)&p.WHu, g_WHu);
    cudaGetSymbolAddress((void**)&p.WLu, g_WLu);
    cudaGetSymbolAddress((void**)&p.WHi, g_WHi);
    cudaGetSymbolAddress((void**)&p.WLi, g_WLi);
    cudaGetSymbolAddress((void**)&p.Auh, g_Auh);
    cudaGetSymbolAddress((void**)&p.Aul, g_Aul);
    cudaGetSymbolAddress((void**)&p.Aih, g_Aih);
    cudaGetSymbolAddress((void**)&p.Ail, g_Ail);
    cudaGetSymbolAddress((void**)&p.rp_i, g_rp_i);
    cudaGetSymbolAddress((void**)&p.rp_u, g_rp_u);
    cudaGetSymbolAddress((void**)&p.srcs_i, g_srcs_i);
    cudaGetSymbolAddress((void**)&p.srcs_u, g_srcs_u);
    cudaGetSymbolAddress((void**)&p.cur_i, g_cur_i);
    cudaGetSymbolAddress((void**)&p.cur_u, g_cur_u);
    cudaGetSymbolAddress((void**)&p.part, g_part);
}

#define SMEM256 (2 * (2 * 128 * 80 + 2 * 32 * (256 * 2 + 16)))
#define SMEM128 (2 * (2 * 128 * 80 + 2 * 32 * (128 * 2 + 16)))
#define EDGE_BLOCKS 592

static const int WOFF[4] = {0, 32768, 98304, 163840};
static const int WSZ[4]  = {32768, 65536, 65536, 32768};
#define VOFF(L) ((L) * FHID * NHEAD)

static void scan(const int* cnt, int n, int* rp, int* part, cudaStream_t st) {
    int nb = (n + 1023) / 1024;
    k_scan_blk<<<nb, 1024, 0, st>>>(cnt, n, rp, part);
    k_scan_part<<<1, 64, 0, st>>>(part, nb);
    k_scan_add<<<nb, 1024, 0, st>>>(rp, part, n);
}

static void split4(const float* X, __nv_bfloat16* xh, __nv_bfloat16* xl, int total,
                   cudaStream_t st) {
    int t4 = total >> 2;
    k_split4<<<(t4 + 255) / 256, 256, 0, st>>>((const float4*)X, (uint2*)xh,
                                               (uint2*)xl, t4);
}

extern "C" void kernel_launch(void* const* d_in, const int* in_sizes, int n_in,
                              void* d_out, int out_size) {
    Ptrs p;
    get_ptrs(p);
    cudaFuncSetAttribute(k_mma_gemm<256, 64>,
                         cudaFuncAttributeMaxDynamicSharedMemorySize, SMEM256);
    cudaFuncSetAttribute(k_mma_gemm<128, 32>,
                         cudaFuncAttributeMaxDynamicSharedMemorySize, SMEM128);

    const float* x_user = (const float*)d_in[0];
    const float* x_item = (const float*)d_in[1];
    const int*   eu     = (const int*)d_in[2];
    const int*   ei     = (const int*)d_in[3];

    bool dictOrder = (in_sizes[5] < 10000);
    const float *Wui[4], *Aui[4], *Wiu[4], *Aiu[4];
    for (int L = 0; L < 4; L++) {
        if (dictOrder) {
            Wui[L] = (const float*)d_in[4 + L * 4 + 0];
            Aui[L] = (const float*)d_in[4 + L * 4 + 1];
            Wiu[L] = (const float*)d_in[4 + L * 4 + 2];
            Aiu[L] = (const float*)d_in[4 + L * 4 + 3];
        } else {
            Wui[L] = (const float*)d_in[4 + L * 4 + 0];
            Wiu[L] = (const float*)d_in[4 + L * 4 + 1];
            Aui[L] = (const float*)d_in[4 + L * 4 + 2];
            Aiu[L] = (const float*)d_in[4 + L * 4 + 3];
        }
    }
    const float* bn_u = (const float*)d_in[20];
    const float* bn_i = (const float*)d_in[21];
    float* out = (float*)d_out;

    cudaStream_t SA = 0;
    cudaStream_t SB = g_si.ok ? g_si.s2 : (cudaStream_t)0;
    bool fork = g_si.ok;
    int ec = 0;
    auto REC = [&](cudaStream_t st) -> int {
        if (!fork) return -1;
        int i = ec++;
        cudaEventRecord(g_si.ev[i], st);
        return i;
    };
    auto WAITE = [&](cudaStream_t st, int i) {
        if (fork && i >= 0) cudaStreamWaitEvent(st, g_si.ev[i], 0);
    };

    // ---- capture-legal fork ----
    int evFork = REC(SA);
    WAITE(SB, evFork);

    // ---- SA prologue ----
    k_zerof<<<6, 256, 0, SA>>>(p.stats_i, 3 * 512);
    split4(x_user, p.Auh, p.Aul, NUSR * FIN0, SA);
    split4(Wui[0], p.WHu + WOFF[0], p.WLu + WOFF[0], WSZ[0], SA);

    // ---- SB prologue ----
    split4(x_item, p.Aih, p.Ail, NITM * FIN0, SB);
    k_zeroi<<<(NUSR + 255) / 256, 256, 0, SB>>>(p.cur_u, NUSR);
    k_zeroi<<<(NITM + 255) / 256, 256, 0, SB>>>(p.cur_i, NITM);
    k_count<<<(NEDG + 255) / 256, 256, 0, SB>>>(eu, ei, p.cur_u, p.cur_i);
    scan(p.cur_i, NITM, p.rp_i, p.part, SB);
    scan(p.cur_u, NUSR, p.rp_u, p.part, SB);
    k_copyi<<<(NITM + 255) / 256, 256, 0, SB>>>(p.rp_i, p.cur_i, NITM);
    k_copyi<<<(NUSR + 255) / 256, 256, 0, SB>>>(p.rp_u, p.cur_u, NUSR);
    k_scatter<<<(NEDG + 255) / 256, 256, 0, SB>>>(eu, ei, p.cur_u, p.cur_i,
                                                  p.srcs_u, p.srcs_i);
    {
        CVArgs cva;
        for (int L = 0; L < 4; L++) {
            cva.W[L] = Wui[L];  cva.A[L] = Aui[L];
            cva.W[4 + L] = Wiu[L];  cva.A[4 + L] = Aiu[L];
        }
        k_collapseAll<<<28, 256, 0, SB>>>(cva, p.Vui, p.Viu);
    }
    int evPre = REC(SB);
    k_zerof<<<6, 256, 0, SB>>>(p.stats_u, 3 * 512);
    split4(Wiu[0], p.WHi + WOFF[0], p.WLi + WOFF[0], WSZ[0], SB);

    const float* cu = x_user;
    const float* ci = x_item;
    int fin = FIN0;
    for (int L = 0; L < 4; L++) {
        int F = (L == 3) ? 128 : 256;
        float* outi = (L == 3) ? (out + (size_t)NUSR * 128) : p.ni;
        float* outu = (L == 3) ? out : p.nu;
        int gbU = (NUSR + 127) / 128, gbI = (NITM + 127) / 128;

        // ---- SA: user GEMM (+el_u) ----
        if (F == 256)
            k_mma_gemm<256, 64><<<gbU, 512, SMEM256, SA>>>(p.Auh, p.Aul,
                p.WHu + WOFF[L], p.WLu + WOFF[L], Aui[L], p.hsu, p.el_u, NUSR, fin);
        else
            k_mma_gemm<128, 32><<<gbU, 256, SMEM128, SA>>>(p.Auh, p.Aul,
                p.WHu + WOFF[L], p.WLu + WOFF[L], Aui[L], p.hsu, p.el_u, NUSR, fin);
        int evAg = REC(SA);

        // ---- SB: item GEMM (+el_i) ----
        if (F == 256)
            k_mma_gemm<256, 64><<<gbI, 512, SMEM256, SB>>>(p.Aih, p.Ail,
                p.WHi + WOFF[L], p.WLi + WOFF[L], Aiu[L], p.hsi, p.el_i, NITM, fin);
        else
            k_mma_gemm<128, 32><<<gbI, 256, SMEM128, SB>>>(p.Aih, p.Ail,
                p.WHi + WOFF[L], p.WLi + WOFF[L], Aiu[L], p.hsi, p.el_i, NITM, fin);
        int evBg = REC(SB);

        // ---- deferred weight splits for L1..3 ----
        if (L == 0) {
            for (int l = 1; l < 4; l++) {
                split4(Wui[l], p.WHu + WOFF[l], p.WLu + WOFF[l], WSZ[l], SA);
                split4(Wiu[l], p.WHi + WOFF[l], p.WLi + WOFF[l], WSZ[l], SB);
            }
        }

        // ---- fused edges ----
        if (L == 0) WAITE(SA, evPre);
        if (F == 256) {
            k_edge256s<<<EDGE_BLOCKS, 256, 0, SA>>>(p.rp_i, p.srcs_i,
                (const float4*)p.el_u, (const float4*)(p.Vui + VOFF(L)), ci,
                p.hsu, outi, p.stats_i + L * 512, NITM, fin);
            k_edge256s<<<EDGE_BLOCKS, 256, 0, SB>>>(p.rp_u, p.srcs_u,
                (const float4*)p.el_i, (const float4*)(p.Viu + VOFF(L)), cu,
                p.hsi, outu, p.stats_u + L * 512, NUSR, fin);
        } else {
            k_edge128f<<<wgrid(NITM), 256, 0, SA>>>(p.rp_i, p.srcs_i,
                (const float4*)p.el_u, (const float4*)(p.Vui + VOFF(L)), ci,
                p.hsu, outi, NITM, fin);
            k_edge128f<<<wgrid(NUSR), 256, 0, SB>>>(p.rp_u, p.srcs_u,
                (const float4*)p.el_i, (const float4*)(p.Viu + VOFF(L)), cu,
                p.hsi, outu, NUSR, fin);
        }

        if (L < 3) {
            WAITE(SA, evBg);
            k_bnapply<<<256, 256, 0, SA>>>(p.ni, p.hi, (uint32_t*)p.Aih,
                                           (uint32_t*)p.Ail, bn_i,
                                           p.stats_i + L * 512, L, NITM,
                                           (L == 2) ? 1 : 0);
            WAITE(SB, evAg);
            k_bnapply<<<256, 256, 0, SB>>>(p.nu, p.hu, (uint32_t*)p.Auh,
                                           (uint32_t*)p.Aul, bn_u,
                                           p.stats_u + L * 512, L, NUSR,
                                           (L == 2) ? 1 : 0);
            int evAe = REC(SA);
            int evBe = REC(SB);
            WAITE(SA, evBe);
            WAITE(SB, evAe);
            cu = p.hu;
            ci = p.hi;
            fin = FHID;
        } else {
            int evBf = REC(SB);
            WAITE(SA, evBf);
        }
    }
    (void)n_in; (void)out_size;
}

// round 14
// speedup vs baseline: 1.0488x; 1.0418x over previous
#include <cuda_runtime.h>
#include <cuda_bf16.h>
#include <math.h>
#include <stddef.h>
#include <stdint.h>

// ---------------- problem constants ----------------
#define NUSR 50000
#define NITM 20000
#define NEDG 400000
#define FIN0 128
#define FHID 256
#define NHEAD 4

// ---------------- device scratch (no allocs allowed) ----------------
__device__ float g_hu [(size_t)NUSR * FHID];
__device__ float g_hi [(size_t)NITM * FHID];
__device__ float g_hsu[(size_t)NUSR * FHID];
__device__ float g_hsi[(size_t)NITM * FHID];
__device__ float g_nu [(size_t)NUSR * FHID];
__device__ float g_ni [(size_t)NITM * FHID];
__device__ float g_el_u[NUSR * 4];
__device__ float g_el_i[NITM * 4];
__device__ int   g_rp_i[NITM + 1];
__device__ int   g_rp_u[NUSR + 1];
__device__ int   g_srcs_i[NEDG];
__device__ int   g_srcs_u[NEDG];
__device__ int   g_cur_i[NITM];
__device__ int   g_cur_u[NUSR];
__device__ float g_Vui[4 * FHID * NHEAD];
__device__ float g_Viu[4 * FHID * NHEAD];
__device__ float g_stats_i[3 * 512];
__device__ float g_stats_u[3 * 512];
__device__ int   g_part[64];
__device__ __nv_bfloat16 g_WHu[196608];
__device__ __nv_bfloat16 g_WLu[196608];
__device__ __nv_bfloat16 g_WHi[196608];
__device__ __nv_bfloat16 g_WLi[196608];
__device__ __nv_bfloat16 g_Auh[(size_t)NUSR * FHID];
__device__ __nv_bfloat16 g_Aul[(size_t)NUSR * FHID];
__device__ __nv_bfloat16 g_Aih[(size_t)NITM * FHID];
__device__ __nv_bfloat16 g_Ail[(size_t)NITM * FHID];

// ---------------- PTX helpers (baseline features only) ----------------
__device__ __forceinline__ uint32_t smem_u32(const void* p) {
    uint32_t a;
    asm("{ .reg .u64 t; cvta.to.shared.u64 t, %1; cvt.u32.u64 %0, t; }"
        : "=r"(a) : "l"(p));
    return a;
}
__device__ __forceinline__ void ldsm4(uint32_t* r, uint32_t addr) {
    asm volatile("ldmatrix.sync.aligned.m8n8.x4.shared.b16 {%0,%1,%2,%3}, [%4];"
        : "=r"(r[0]), "=r"(r[1]), "=r"(r[2]), "=r"(r[3]) : "r"(addr));
}
__device__ __forceinline__ void ldsm4t(uint32_t* r, uint32_t addr) {
    asm volatile("ldmatrix.sync.aligned.m8n8.x4.trans.shared.b16 {%0,%1,%2,%3}, [%4];"
        : "=r"(r[0]), "=r"(r[1]), "=r"(r[2]), "=r"(r[3]) : "r"(addr));
}
__device__ __forceinline__ void mma16816(float* c, const uint32_t* a,
                                         uint32_t b0, uint32_t b1) {
    asm volatile(
        "mma.sync.aligned.m16n8k16.row.col.f32.bf16.bf16.f32 "
        "{%0,%1,%2,%3}, {%4,%5,%6,%7}, {%8,%9}, {%0,%1,%2,%3};"
        : "+f"(c[0]), "+f"(c[1]), "+f"(c[2]), "+f"(c[3])
        : "r"(a[0]), "r"(a[1]), "r"(a[2]), "r"(a[3]), "r"(b0), "r"(b1));
}
#define CPA16(dst, src) \
    asm volatile("cp.async.cg.shared.global [%0], [%1], 16;" \
                 :: "r"(dst), "l"(src))
#define CP_COMMIT() asm volatile("cp.async.commit_group;")
#define CP_WAIT1()  asm volatile("cp.async.wait_group 1;" ::: "memory")
#define CP_WAIT0()  asm volatile("cp.async.wait_group 0;" ::: "memory")

__device__ __forceinline__ uint32_t pack_bf16x2(float a, float b) {
    return ((uint32_t)__bfloat16_as_ushort(__float2bfloat16_rn(b)) << 16) |
           __bfloat16_as_ushort(__float2bfloat16_rn(a));
}
__device__ __forceinline__ float fast_tanh(float x) {
    x = fminf(fmaxf(x, -15.f), 15.f);
    float e = __expf(2.f * x);
    return (e - 1.f) / (e + 1.f);
}

// ---------------- tiny utility kernels ----------------
__global__ void k_noop() {}
__global__ void k_zeroi(int* p, int n) {
    int i = blockIdx.x * blockDim.x + threadIdx.x;
    if (i < n) p[i] = 0;
}
__global__ void k_zerof(float* p, int n) {
    int i = blockIdx.x * blockDim.x + threadIdx.x;
    if (i < n) p[i] = 0.f;
}

// ---------------- CSR construction ----------------
__global__ void k_count(const int* __restrict__ eu, const int* __restrict__ ei,
                        int* cu, int* ci) {
    int k = blockIdx.x * blockDim.x + threadIdx.x;
    if (k < NEDG) {
        atomicAdd(&ci[ei[k]], 1);
        atomicAdd(&cu[eu[k]], 1);
    }
}
__global__ void k_scan_blk(const int* __restrict__ cnt, int n,
                           int* __restrict__ rp, int* __restrict__ part) {
    __shared__ int ws[32];
    int tid = threadIdx.x;
    int i = blockIdx.x * 1024 + tid;
    int v = (i < n) ? cnt[i] : 0;
    int lane = tid & 31, w = tid >> 5;
    int x = v;
    #pragma unroll
    for (int o = 1; o < 32; o <<= 1) {
        int y = __shfl_up_sync(0xffffffffu, x, o);
        if (lane >= o) x += y;
    }
    if (lane == 31) ws[w] = x;
    __syncthreads();
    if (w == 0) {
        int t = ws[lane];
        #pragma unroll
        for (int o = 1; o < 32; o <<= 1) {
            int y = __shfl_up_sync(0xffffffffu, t, o);
            if (lane >= o) t += y;
        }
        ws[lane] = t;
    }
    __syncthreads();
    int incl = x + (w > 0 ? ws[w - 1] : 0);
    if (i < n) rp[i + 1] = incl;
    if (tid == 1023) part[blockIdx.x] = incl;
}
__global__ void k_scan_part(int* part, int nb) {
    __shared__ int w0sum;
    int tid = threadIdx.x;
    int v = (tid < nb) ? part[tid] : 0;
    int lane = tid & 31, w = tid >> 5;
    int x = v;
    #pragma unroll
    for (int o = 1; o < 32; o <<= 1) {
        int y = __shfl_up_sync(0xffffffffu, x, o);
        if (lane >= o) x += y;
    }
    if (w == 0 && lane == 31) w0sum = x;
    __syncthreads();
    int incl = x + (w ? w0sum : 0);
    if (tid < nb) part[tid] = incl - v;
}
// writes rp[i+1] final value AND cur[i] = rp[i] (scatter cursor) in one pass
__global__ void k_scan_add(int* __restrict__ rp, const int* __restrict__ part,
                           int* __restrict__ cur, int n) {
    int i = blockIdx.x * 1024 + threadIdx.x;
    if (i < n) {
        int v = rp[i + 1] + part[blockIdx.x];
        rp[i + 1] = v;
        // exclusive start for element i+1 is v; element 0 start is 0
        if (i + 1 < n) cur[i + 1] = v;
    }
    if (i == 0) { rp[0] = 0; cur[0] = 0; }
}
__global__ void k_scatter(const int* __restrict__ eu, const int* __restrict__ ei,
                          int* cu, int* ci,
                          int* __restrict__ su, int* __restrict__ si) {
    int k = blockIdx.x * blockDim.x + threadIdx.x;
    if (k < NEDG) {
        int u = eu[k], it = ei[k];
        int p = atomicAdd(&ci[it], 1);
        si[p] = u;
        int q = atomicAdd(&cu[u], 1);
        su[q] = it;
    }
}

// ------- vectorized fp32 -> bf16 hi/lo split: 4 elems per thread -------
__global__ void k_split4(const float4* __restrict__ X, uint2* __restrict__ xh,
                         uint2* __restrict__ xl, int total4) {
    int id = blockIdx.x * blockDim.x + threadIdx.x;
    if (id >= total4) return;
    float4 v = X[id];
    float hx = __bfloat162float(__float2bfloat16_rn(v.x));
    float hy = __bfloat162float(__float2bfloat16_rn(v.y));
    float hz = __bfloat162float(__float2bfloat16_rn(v.z));
    float hw = __bfloat162float(__float2bfloat16_rn(v.w));
    xh[id] = make_uint2(pack_bf16x2(v.x, v.y), pack_bf16x2(v.z, v.w));
    xl[id] = make_uint2(pack_bf16x2(v.x - hx, v.y - hy),
                        pack_bf16x2(v.z - hz, v.w - hw));
}

// ---------------- batched collapseV ----------------
struct CVArgs { const float* W[8]; const float* A[8]; };
__global__ void k_collapseAll(CVArgs a, float* __restrict__ Vui,
                              float* __restrict__ Viu) {
    int t = blockIdx.x * blockDim.x + threadIdx.x;
    if (t >= 7168) return;
    int side = (t >= 3584) ? 1 : 0;
    int u = t - side * 3584;
    int L, off;
    if (u < 512)       { L = 0; off = 0; }
    else if (u < 1536) { L = 1; off = 512; }
    else if (u < 2560) { L = 2; off = 1536; }
    else               { L = 3; off = 2560; }
    int local = u - off;
    int k = local >> 2, h = local & 3;
    int F = (L == 3) ? 128 : 256;
    int dh = (L == 3) ? 32 : 64;
    const float* W = a.W[side * 4 + L];
    const float* A1 = a.A[side * 4 + L] + NHEAD * dh;
    float s = 0.f;
    for (int d = 0; d < dh; d++)
        s += W[(size_t)k * F + h * dh + d] * A1[h * dh + d];
    (side ? Viu : Vui)[L * FHID * NHEAD + local] = s;
}

// ---------------- tensor-core GEMM + fused el epilogue ----------------
template <int BN, int DH>
__global__ void __launch_bounds__((BN == 256) ? 512 : 256, 1)
k_mma_gemm(const __nv_bfloat16* __restrict__ Ah, const __nv_bfloat16* __restrict__ Al,
           const __nv_bfloat16* __restrict__ Bh, const __nv_bfloat16* __restrict__ Bl,
           const float* __restrict__ attA,
           float* __restrict__ C, float* __restrict__ el, int M, int K) {
    constexpr int NT = (BN == 256) ? 512 : 256;
    constexpr int SBSTR = BN * 2 + 16;
    constexpr int ASZ = 128 * 80;
    constexpr int BOFF = 2 * ASZ;
    constexpr int BSZ = 32 * SBSTR;
    constexpr int STAGE = BOFF + 2 * BSZ;
    constexpr int NBC = 32 * (BN / 8);

    extern __shared__ char smem[];
    uint32_t sb = smem_u32(smem);
    int tid = threadIdx.x;
    int wid = tid >> 5, lane = tid & 31;
    int wm = wid & 3, wn = wid >> 2;
    int bm = blockIdx.x * 128;

    float acc[2][8][4];
    #pragma unroll
    for (int i = 0; i < 2; i++)
        #pragma unroll
        for (int j = 0; j < 8; j++)
            #pragma unroll
            for (int q = 0; q < 4; q++) acc[i][j][q] = 0.f;

    int nch = K >> 5;

    auto load_stage = [&](int st, int kc) {
        uint32_t sbase = sb + st * STAGE;
        int k0 = kc << 5;
        #pragma unroll
        for (int c = tid; c < 512; c += NT) {
            int row = c >> 2, q = c & 3;
            int gr = bm + row;
            gr = gr < M ? gr : M - 1;
            size_t gi = (size_t)gr * K + k0 + q * 8;
            uint32_t d = sbase + row * 80 + q * 16;
            CPA16(d, Ah + gi);
            CPA16(d + ASZ, Al + gi);
        }
        #pragma unroll
        for (int c = tid; c < NBC; c += NT) {
            int k = c / (BN / 8), seg = c % (BN / 8);
            size_t gi = (size_t)(k0 + k) * BN + seg * 8;
            uint32_t d = sbase + BOFF + k * SBSTR + seg * 16;
            CPA16(d, Bh + gi);
            CPA16(d + BSZ, Bl + gi);
        }
        CP_COMMIT();
    };

    load_stage(0, 0);
    for (int kc = 0; kc < nch; kc++) {
        int cur = kc & 1;
        if (kc + 1 < nch) {
            load_stage(1 - cur, kc + 1);
            CP_WAIT1();
        } else {
            CP_WAIT0();
        }
        __syncthreads();
        uint32_t abase = sb + cur * STAGE;
        #pragma unroll
        for (int s = 0; s < 2; s++) {
            uint32_t Af[2][4], Alf[2][4];
            #pragma unroll
            for (int mt = 0; mt < 2; mt++) {
                uint32_t ad = abase +
                    (uint32_t)(wm * 32 + mt * 16 + (lane & 15)) * 80 +
                    s * 32 + (lane >> 4) * 16;
                ldsm4(Af[mt], ad);
                ldsm4(Alf[mt], ad + ASZ);
            }
            #pragma unroll
            for (int np = 0; np < 4; np++) {
                int g = lane >> 3, r = lane & 7;
                int kk = s * 16 + (g & 1) * 8 + r;
                int nn = wn * 64 + np * 16 + (g >> 1) * 8;
                uint32_t bd = abase + BOFF + (uint32_t)kk * SBSTR + nn * 2;
                uint32_t bh4[4], bl4[4];
                ldsm4t(bh4, bd);
                ldsm4t(bl4, bd + BSZ);
                #pragma unroll
                for (int mt = 0; mt < 2; mt++)
                    #pragma unroll
                    for (int sub = 0; sub < 2; sub++) {
                        float* a = acc[mt][np * 2 + sub];
                        mma16816(a, Af[mt], bh4[2 * sub], bh4[2 * sub + 1]);
                        mma16816(a, Af[mt], bl4[2 * sub], bl4[2 * sub + 1]);
                        mma16816(a, Alf[mt], bh4[2 * sub], bh4[2 * sub + 1]);
                    }
            }
        }
        __syncthreads();
    }

    constexpr int HPW = 64 / DH;
    int grp = lane >> 2, tq = lane & 3;
    #pragma unroll
    for (int mt = 0; mt < 2; mt++) {
        int r0 = bm + wm * 32 + mt * 16 + grp;
        int r1 = r0 + 8;
        #pragma unroll
        for (int nt = 0; nt < 8; nt++) {
            int col = wn * 64 + nt * 8 + tq * 2;
            if (r0 < M)
                *(float2*)(C + (size_t)r0 * BN + col) =
                    make_float2(acc[mt][nt][0], acc[mt][nt][1]);
            if (r1 < M)
                *(float2*)(C + (size_t)r1 * BN + col) =
                    make_float2(acc[mt][nt][2], acc[mt][nt][3]);
        }
        float s0[HPW], s1[HPW];
        #pragma unroll
        for (int p = 0; p < HPW; p++) { s0[p] = 0.f; s1[p] = 0.f; }
        #pragma unroll
        for (int nt = 0; nt < 8; nt++) {
            int part = (nt * 8) / DH;
            int col = wn * 64 + nt * 8 + tq * 2;
            float c0 = attA[col], c1 = attA[col + 1];
            s0[part] += c0 * acc[mt][nt][0] + c1 * acc[mt][nt][1];
            s1[part] += c0 * acc[mt][nt][2] + c1 * acc[mt][nt][3];
        }
        #pragma unroll
        for (int p = 0; p < HPW; p++) {
            s0[p] += __shfl_xor_sync(0xffffffffu, s0[p], 1);
            s0[p] += __shfl_xor_sync(0xffffffffu, s0[p], 2);
            s1[p] += __shfl_xor_sync(0xffffffffu, s1[p], 1);
            s1[p] += __shfl_xor_sync(0xffffffffu, s1[p], 2);
            if (tq == 0) {
                int h = wn * HPW + p;
                if (r0 < M) el[r0 * 4 + h] = s0[p];
                if (r1 < M) el[r1 * 4 + h] = s1[p];
            }
        }
    }
}

__device__ __forceinline__ float lrelu(float x, float s) { return x > 0.f ? x : s * x; }

// ---- fused edge kernel, F=256: er + 1-pass softmax-agg + BN stats (R11 form) ----
__global__ void __launch_bounds__(256)
k_edge256s(const int* __restrict__ rp, const int* __restrict__ srcs,
           const float4* __restrict__ el4, const float4* __restrict__ V4,
           const float* __restrict__ cdst, const float* __restrict__ hs,
           float* __restrict__ out, float* __restrict__ stats,
           int ndst, int fin) {
    __shared__ float s_st[512];
    int tid = threadIdx.x;
    for (int i = tid; i < 512; i += 256) s_st[i] = 0.f;
    __syncthreads();
    int lane = tid & 31, wloc = tid >> 5;
    bool loHalf = lane < 16;
    float sm0[4] = {0.f, 0.f, 0.f, 0.f}, sq0[4] = {0.f, 0.f, 0.f, 0.f};
    float sm1[4] = {0.f, 0.f, 0.f, 0.f}, sq1[4] = {0.f, 0.f, 0.f, 0.f};

    for (int w = blockIdx.x * 8 + wloc; w < ndst; w += gridDim.x * 8) {
        const float* c = cdst + (size_t)w * fin;
        float a0 = 0.f, a1 = 0.f, a2 = 0.f, a3 = 0.f;
        for (int k = lane; k < fin; k += 32) {
            float xv = c[k];
            float4 v = V4[k];
            a0 += xv * v.x; a1 += xv * v.y; a2 += xv * v.z; a3 += xv * v.w;
        }
        #pragma unroll
        for (int o = 16; o; o >>= 1) {
            a0 += __shfl_xor_sync(0xffffffffu, a0, o);
            a1 += __shfl_xor_sync(0xffffffffu, a1, o);
            a2 += __shfl_xor_sync(0xffffffffu, a2, o);
            a3 += __shfl_xor_sync(0xffffffffu, a3, o);
        }
        float erA = loHalf ? a0 : a1, erB = loHalf ? a2 : a3;

        int s0 = rp[w], s1 = rp[w + 1];
        float4 o0 = make_float4(0.f, 0.f, 0.f, 0.f);
        float4 o1 = make_float4(0.f, 0.f, 0.f, 0.f);
        if (s0 != s1) {
            float4 acc0 = make_float4(0.f, 0.f, 0.f, 0.f);
            float4 acc1 = make_float4(0.f, 0.f, 0.f, 0.f);
            float zA = 0.f, zB = 0.f;
            for (int j = s0; j < s1; j++) {
                int s = srcs[j];
                float4 e = el4[s];
                float eA = loHalf ? e.x : e.y, eB = loHalf ? e.z : e.w;
                float aA = __expf(lrelu(eA + erA, 0.2f));
                float aB = __expf(lrelu(eB + erB, 0.2f));
                const float4* row = (const float4*)(hs + (size_t)s * 256);
                float4 v0 = row[lane];
                float4 v1 = row[lane + 32];
                acc0.x += aA * v0.x; acc0.y += aA * v0.y;
                acc0.z += aA * v0.z; acc0.w += aA * v0.w;
                acc1.x += aB * v1.x; acc1.y += aB * v1.y;
                acc1.z += aB * v1.z; acc1.w += aB * v1.w;
                zA += aA; zB += aB;
            }
            float iA = 1.f / zA, iB = 1.f / zB;
            o0 = make_float4(acc0.x * iA, acc0.y * iA, acc0.z * iA, acc0.w * iA);
            o1 = make_float4(acc1.x * iB, acc1.y * iB, acc1.z * iB, acc1.w * iB);
        }
        float4* op = (float4*)(out + (size_t)w * 256);
        op[lane] = o0;
        op[lane + 32] = o1;
        sm0[0] += o0.x; sq0[0] += o0.x * o0.x;
        sm0[1] += o0.y; sq0[1] += o0.y * o0.y;
        sm0[2] += o0.z; sq0[2] += o0.z * o0.z;
        sm0[3] += o0.w; sq0[3] += o0.w * o0.w;
        sm1[0] += o1.x; sq1[0] += o1.x * o1.x;
        sm1[1] += o1.y; sq1[1] += o1.y * o1.y;
        sm1[2] += o1.z; sq1[2] += o1.z * o1.z;
        sm1[3] += o1.w; sq1[3] += o1.w * o1.w;
    }
    #pragma unroll
    for (int q = 0; q < 4; q++) {
        atomicAdd(&s_st[lane * 4 + q], sm0[q]);
        atomicAdd(&s_st[256 + lane * 4 + q], sq0[q]);
        atomicAdd(&s_st[128 + lane * 4 + q], sm1[q]);
        atomicAdd(&s_st[256 + 128 + lane * 4 + q], sq1[q]);
    }
    __syncthreads();
    for (int i = tid; i < 512; i += 256)
        atomicAdd(&stats[i], s_st[i]);
}

// ---- fused edge kernel, F=128 (dh=32): er + 1-pass softmax-agg (R11 form) ----
__global__ void k_edge128f(const int* __restrict__ rp, const int* __restrict__ srcs,
                           const float4* __restrict__ el4, const float4* __restrict__ V4,
                           const float* __restrict__ cdst, const float* __restrict__ hs,
                           float* __restrict__ out, int ndst, int fin) {
    int w = (blockIdx.x * blockDim.x + threadIdx.x) >> 5;
    int lane = threadIdx.x & 31;
    if (w >= ndst) return;
    const float* c = cdst + (size_t)w * fin;
    float a0 = 0.f, a1 = 0.f, a2 = 0.f, a3 = 0.f;
    for (int k = lane; k < fin; k += 32) {
        float xv = c[k];
        float4 v = V4[k];
        a0 += xv * v.x; a1 += xv * v.y; a2 += xv * v.z; a3 += xv * v.w;
    }
    #pragma unroll
    for (int o = 16; o; o >>= 1) {
        a0 += __shfl_xor_sync(0xffffffffu, a0, o);
        a1 += __shfl_xor_sync(0xffffffffu, a1, o);
        a2 += __shfl_xor_sync(0xffffffffu, a2, o);
        a3 += __shfl_xor_sync(0xffffffffu, a3, o);
    }
    int hsel = lane >> 3;
    float erS = (hsel == 0) ? a0 : (hsel == 1) ? a1 : (hsel == 2) ? a2 : a3;

    int s0 = rp[w], s1 = rp[w + 1];
    float4* o = (float4*)(out + (size_t)w * 128);
    if (s0 == s1) {
        o[lane] = make_float4(0.f, 0.f, 0.f, 0.f);
        return;
    }
    float4 acc = make_float4(0.f, 0.f, 0.f, 0.f);
    float z = 0.f;
    for (int j = s0; j < s1; j++) {
        int s = srcs[j];
        float4 e = el4[s];
        float eS = (hsel == 0) ? e.x : (hsel == 1) ? e.y : (hsel == 2) ? e.z : e.w;
        float a = __expf(lrelu(eS + erS, 0.2f));
        const float4* row = (const float4*)(hs + (size_t)s * 128);
        float4 v = row[lane];
        acc.x += a * v.x; acc.y += a * v.y; acc.z += a * v.z; acc.w += a * v.w;
        z += a;
    }
    float iz = 1.f / z;
    o[lane] = make_float4(acc.x * iz, acc.y * iz, acc.z * iz, acc.w * iz);
}

// ------- BN apply (+act +bf16 split), 2 columns/thread, packed stores -------
__global__ void k_bnapply(const float* __restrict__ x, float* __restrict__ y,
                          uint32_t* __restrict__ yh, uint32_t* __restrict__ yl,
                          const float* __restrict__ bn, const float* __restrict__ stats,
                          int L, int n, int use_tanh) {
    int tid = threadIdx.x;
    int cp = (tid & 127) * 2;
    int rh = tid >> 7;
    float inv_n = 1.f / (float)n;
    float mu0 = stats[cp] * inv_n;
    float mu1 = stats[cp + 1] * inv_n;
    float var0 = stats[256 + cp] * inv_n - mu0 * mu0;
    float var1 = stats[256 + cp + 1] * inv_n - mu1 * mu1;
    float g0 = bn[(L * 2 + 0) * 256 + cp], g1 = bn[(L * 2 + 0) * 256 + cp + 1];
    float b0 = bn[(L * 2 + 1) * 256 + cp], b1 = bn[(L * 2 + 1) * 256 + cp + 1];
    float sc0 = g0 * rsqrtf(var0 + 1e-5f), sc1 = g1 * rsqrtf(var1 + 1e-5f);
    float sh0 = b0 - mu0 * sc0, sh1 = b1 - mu1 * sc1;
    for (int r = blockIdx.x * 2 + rh; r < n; r += gridDim.x * 2) {
        size_t idx = (size_t)r * 256 + cp;
        float2 v = *(const float2*)(x + idx);
        float v0 = sc0 * v.x + sh0;
        float v1 = sc1 * v.y + sh1;
        if (use_tanh) { v0 = fast_tanh(v0); v1 = fast_tanh(v1); }
        else {
            v0 = v0 > 0.f ? v0 : 0.01f * v0;
            v1 = v1 > 0.f ? v1 : 0.01f * v1;
        }
        *(float2*)(y + idx) = make_float2(v0, v1);
        float h0 = __bfloat162float(__float2bfloat16_rn(v0));
        float h1 = __bfloat162float(__float2bfloat16_rn(v1));
        yh[idx >> 1] = pack_bf16x2(v0, v1);
        yl[idx >> 1] = pack_bf16x2(v0 - h0, v1 - h1);
    }
}

// ---------------- static stream/event setup (pre-checkpoint) ----------------
namespace {
struct StreamInit {
    cudaStream_t s2 = 0;
    cudaEvent_t ev[32];
    bool ok = false;
    StreamInit() {
        if (cudaStreamCreateWithFlags(&s2, cudaStreamNonBlocking) != cudaSuccess) return;
        for (int i = 0; i < 32; i++)
            if (cudaEventCreateWithFlags(&ev[i], cudaEventDisableTiming) != cudaSuccess)
                return;
        k_noop<<<1, 32>>>();
        k_noop<<<1, 32, 0, s2>>>();
        for (int i = 0; i < 32; i++) cudaEventRecord(ev[i], (i & 1) ? s2 : 0);
        if (cudaDeviceSynchronize() != cudaSuccess) return;
        if (cudaGetLastError() != cudaSuccess) return;
        ok = true;
    }
};
StreamInit g_si;
}

// ---------------- host orchestration ----------------
static inline int wgrid(int nwarp) { return (nwarp * 32 + 255) / 256; }

struct Ptrs {
    float *hu, *hi, *hsu, *hsi, *nu, *ni;
    float *el_u, *el_i, *Vui, *Viu, *stats_i, *stats_u;
    __nv_bfloat16 *WHu, *WLu, *WHi, *WLi, *Auh, *Aul, *Aih, *Ail;
    int *rp_i, *rp_u, *srcs_i, *srcs_u, *cur_i, *cur_u, *part;
};

static void get_ptrs(Ptrs& p) {
    cudaGetSymbolAddress((void**)&p.hu, g_hu);
    cudaGetSymbolAddress((void**)&p.hi, g_hi);
    cudaGetSymbolAddress((void**)&p.hsu, g_hsu);
    cudaGetSymbolAddress((void**)&p.hsi, g_hsi);
    cudaGetSymbolAddress((void**)&p.nu, g_nu);
    cudaGetSymbolAddress((void**)&p.ni, g_ni);
    cudaGetSymbolAddress((void**)&p.el_u, g_el_u);
    cudaGetSymbolAddress((void**)&p.el_i, g_el_i);
    cudaGetSymbolAddress((void**)&p.Vui, g_Vui);
    cudaGetSymbolAddress((void**)&p.Viu, g_Viu);
    cudaGetSymbolAddress((void**)&p.stats_i, g_stats_i);
    cudaGetSymbolAddress((void**)&p.stats_u, g_stats_u);
    cudaGetSymbolAddress((void**)&p.WHu, g_WHu);
    cudaGetSymbolAddress((void**)&p.WLu, g_WLu);
    cudaGetSymbolAddress((void**)&p.WHi, g_WHi);
    cudaGetSymbolAddress((void**)&p.WLi, g_WLi);
    cudaGetSymbolAddress((void**)&p.Auh, g_Auh);
    cudaGetSymbolAddress((void**)&p.Aul, g_Aul);
    cudaGetSymbolAddress((void**)&p.Aih, g_Aih);
    cudaGetSymbolAddress((void**)&p.Ail, g_Ail);
    cudaGetSymbolAddress((void**)&p.rp_i, g_rp_i);
    cudaGetSymbolAddress((void**)&p.rp_u, g_rp_u);
    cudaGetSymbolAddress((void**)&p.srcs_i, g_srcs_i);
    cudaGetSymbolAddress((void**)&p.srcs_u, g_srcs_u);
    cudaGetSymbolAddress((void**)&p.cur_i, g_cur_i);
    cudaGetSymbolAddress((void**)&p.cur_u, g_cur_u);
    cudaGetSymbolAddress((void**)&p.part, g_part);
}

#define SMEM256 (2 * (2 * 128 * 80 + 2 * 32 * (256 * 2 + 16)))
#define SMEM128 (2 * (2 * 128 * 80 + 2 * 32 * (128 * 2 + 16)))
#define EDGE_BLOCKS 592

static const int WOFF[4] = {0, 32768, 98304, 163840};
static const int WSZ[4]  = {32768, 65536, 65536, 32768};
#define VOFF(L) ((L) * FHID * NHEAD)

static void scan(const int* cnt, int n, int* rp, int* part, int* cur,
                 cudaStream_t st) {
    int nb = (n + 1023) / 1024;
    k_scan_blk<<<nb, 1024, 0, st>>>(cnt, n, rp, part);
    k_scan_part<<<1, 64, 0, st>>>(part, nb);
    k_scan_add<<<nb, 1024, 0, st>>>(rp, part, cur, n);
}

static void split4(const float* X, __nv_bfloat16* xh, __nv_bfloat16* xl, int total,
                   cudaStream_t st) {
    int t4 = total >> 2;
    k_split4<<<(t4 + 255) / 256, 256, 0, st>>>((const float4*)X, (uint2*)xh,
                                               (uint2*)xl, t4);
}

extern "C" void kernel_launch(void* const* d_in, const int* in_sizes, int n_in,
                              void* d_out, int out_size) {
    Ptrs p;
    get_ptrs(p);
    cudaFuncSetAttribute(k_mma_gemm<256, 64>,
                         cudaFuncAttributeMaxDynamicSharedMemorySize, SMEM256);
    cudaFuncSetAttribute(k_mma_gemm<128, 32>,
                         cudaFuncAttributeMaxDynamicSharedMemorySize, SMEM128);

    const float* x_user = (const float*)d_in[0];
    const float* x_item = (const float*)d_in[1];
    const int*   eu     = (const int*)d_in[2];
    const int*   ei     = (const int*)d_in[3];

    bool dictOrder = (in_sizes[5] < 10000);
    const float *Wui[4], *Aui[4], *Wiu[4], *Aiu[4];
    for (int L = 0; L < 4; L++) {
        if (dictOrder) {
            Wui[L] = (const float*)d_in[4 + L * 4 + 0];
            Aui[L] = (const float*)d_in[4 + L * 4 + 1];
            Wiu[L] = (const float*)d_in[4 + L * 4 + 2];
            Aiu[L] = (const float*)d_in[4 + L * 4 + 3];
        } else {
            Wui[L] = (const float*)d_in[4 + L * 4 + 0];
            Wiu[L] = (const float*)d_in[4 + L * 4 + 1];
            Aui[L] = (const float*)d_in[4 + L * 4 + 2];
            Aiu[L] = (const float*)d_in[4 + L * 4 + 3];
        }
    }
    const float* bn_u = (const float*)d_in[20];
    const float* bn_i = (const float*)d_in[21];
    float* out = (float*)d_out;

    cudaStream_t SA = 0;
    cudaStream_t SB = g_si.ok ? g_si.s2 : (cudaStream_t)0;
    bool fork = g_si.ok;
    int ec = 0;
    auto REC = [&](cudaStream_t st) -> int {
        if (!fork) return -1;
        int i = ec++;
        cudaEventRecord(g_si.ev[i], st);
        return i;
    };
    auto WAITE = [&](cudaStream_t st, int i) {
        if (fork && i >= 0) cudaStreamWaitEvent(st, g_si.ev[i], 0);
    };

    // ---- capture-legal fork ----
    int evFork = REC(SA);
    WAITE(SB, evFork);

    // ---- SA prologue ----
    k_zerof<<<6, 256, 0, SA>>>(p.stats_i, 3 * 512);
    split4(x_user, p.Auh, p.Aul, NUSR * FIN0, SA);
    split4(Wui[0], p.WHu + WOFF[0], p.WLu + WOFF[0], WSZ[0], SA);

    // ---- SB prologue ----
    split4(x_item, p.Aih, p.Ail, NITM * FIN0, SB);
    k_zeroi<<<(NUSR + 255) / 256, 256, 0, SB>>>(p.cur_u, NUSR);
    k_zeroi<<<(NITM + 255) / 256, 256, 0, SB>>>(p.cur_i, NITM);
    k_count<<<(NEDG + 255) / 256, 256, 0, SB>>>(eu, ei, p.cur_u, p.cur_i);
    scan(p.cur_i, NITM, p.rp_i, p.part, p.cur_i, SB);
    scan(p.cur_u, NUSR, p.rp_u, p.part, p.cur_u, SB);
    k_scatter<<<(NEDG + 255) / 256, 256, 0, SB>>>(eu, ei, p.cur_u, p.cur_i,
                                                  p.srcs_u, p.srcs_i);
    {
        CVArgs cva;
        for (int L = 0; L < 4; L++) {
            cva.W[L] = Wui[L];  cva.A[L] = Aui[L];
            cva.W[4 + L] = Wiu[L];  cva.A[4 + L] = Aiu[L];
        }
        k_collapseAll<<<28, 256, 0, SB>>>(cva, p.Vui, p.Viu);
    }
    int evPre = REC(SB);
    k_zerof<<<6, 256, 0, SB>>>(p.stats_u, 3 * 512);
    split4(Wiu[0], p.WHi + WOFF[0], p.WLi + WOFF[0], WSZ[0], SB);

    const float* cu = x_user;
    const float* ci = x_item;
    int fin = FIN0;
    for (int L = 0; L < 4; L++) {
        int F = (L == 3) ? 128 : 256;
        float* outi = (L == 3) ? (out + (size_t)NUSR * 128) : p.ni;
        float* outu = (L == 3) ? out : p.nu;
        int gbU = (NUSR + 127) / 128, gbI = (NITM + 127) / 128;

        // ---- SA: user GEMM (+el_u) ----
        if (F == 256)
            k_mma_gemm<256, 64><<<gbU, 512, SMEM256, SA>>>(p.Auh, p.Aul,
                p.WHu + WOFF[L], p.WLu + WOFF[L], Aui[L], p.hsu, p.el_u, NUSR, fin);
        else
            k_mma_gemm<128, 32><<<gbU, 256, SMEM128, SA>>>(p.Auh, p.Aul,
                p.WHu + WOFF[L], p.WLu + WOFF[L], Aui[L], p.hsu, p.el_u, NUSR, fin);
        int evAg = REC(SA);

        // ---- SB: item GEMM (+el_i) ----
        if (F == 256)
            k_mma_gemm<256, 64><<<gbI, 512, SMEM256, SB>>>(p.Aih, p.Ail,
                p.WHi + WOFF[L], p.WLi + WOFF[L], Aiu[L], p.hsi, p.el_i, NITM, fin);
        else
            k_mma_gemm<128, 32><<<gbI, 256, SMEM128, SB>>>(p.Aih, p.Ail,
                p.WHi + WOFF[L], p.WLi + WOFF[L], Aiu[L], p.hsi, p.el_i, NITM, fin);
        int evBg = REC(SB);

        // ---- fused edges FIRST (critical path), deferred splits after ----
        if (L == 0) WAITE(SA, evPre);
        if (F == 256) {
            k_edge256s<<<EDGE_BLOCKS, 256, 0, SA>>>(p.rp_i, p.srcs_i,
                (const float4*)p.el_u, (const float4*)(p.Vui + VOFF(L)), ci,
                p.hsu, outi, p.stats_i + L * 512, NITM, fin);
            k_edge256s<<<EDGE_BLOCKS, 256, 0, SB>>>(p.rp_u, p.srcs_u,
                (const float4*)p.el_i, (const float4*)(p.Viu + VOFF(L)), cu,
                p.hsi, outu, p.stats_u + L * 512, NUSR, fin);
        } else {
            k_edge128f<<<wgrid(NITM), 256, 0, SA>>>(p.rp_i, p.srcs_i,
                (const float4*)p.el_u, (const float4*)(p.Vui + VOFF(L)), ci,
                p.hsu, outi, NITM, fin);
            k_edge128f<<<wgrid(NUSR), 256, 0, SB>>>(p.rp_u, p.srcs_u,
                (const float4*)p.el_i, (const float4*)(p.Viu + VOFF(L)), cu,
                p.hsi, outu, NUSR, fin);
        }

        if (L < 3) {
            WAITE(SA, evBg);
            k_bnapply<<<256, 256, 0, SA>>>(p.ni, p.hi, (uint32_t*)p.Aih,
                                           (uint32_t*)p.Ail, bn_i,
                                           p.stats_i + L * 512, L, NITM,
                                           (L == 2) ? 1 : 0);
            WAITE(SB, evAg);
            k_bnapply<<<256, 256, 0, SB>>>(p.nu, p.hu, (uint32_t*)p.Auh,
                                           (uint32_t*)p.Aul, bn_u,
                                           p.stats_u + L * 512, L, NUSR,
                                           (L == 2) ? 1 : 0);
            // deferred weight splits for L1..3, after the L0 critical stages
            if (L == 0) {
                for (int l = 1; l < 4; l++) {
                    split4(Wui[l], p.WHu + WOFF[l], p.WLu + WOFF[l], WSZ[l], SA);
                    split4(Wiu[l], p.WHi + WOFF[l], p.WLi + WOFF[l], WSZ[l], SB);
                }
            }
            int evAe = REC(SA);
            int evBe = REC(SB);
            WAITE(SA, evBe);
            WAITE(SB, evAe);
            cu = p.hu;
            ci = p.hi;
            fin = FHID;
        } else {
            int evBf = REC(SB);
            WAITE(SA, evBf);
        }
    }
    (void)n_in; (void)out_size;
}